// round 1
// baseline (speedup 1.0000x reference)
#include <cuda_runtime.h>
#include <math.h>

#define HIDDEN 4096
#define NH 32
#define NKV 8
#define HD 128
#define BB 2
#define SS 2048
#define MROWS (BB*SS)   /* 4096 */

// ---------------- scratch (static __device__, allocation-guard safe) -----------
__device__ float g_Q[(size_t)MROWS * NH * HD];   // 64 MB  [b,s,h,d]
__device__ float g_K[(size_t)MROWS * NKV * HD];  // 16 MB  [b,s,kh,d]
__device__ float g_V[(size_t)MROWS * NKV * HD];  // 16 MB
__device__ float g_A[(size_t)MROWS * NH * HD];   // 64 MB  attn out [b,s,h,d]

// ---------------- SGEMM: C[M,N] = A[M,K] * W[N,K]^T ---------------------------
// classic 128x128x16, 8x8 per thread, 256 threads
__global__ __launch_bounds__(256) void sgemm_nt(
    const float* __restrict__ A, const float* __restrict__ W,
    float* __restrict__ C, int M, int N, int K)
{
    const int BM = 128, BN = 128, BK = 16;
    __shared__ float As[BK][BM + 1];
    __shared__ float Bs[BK][BN + 1];

    int tid = threadIdx.x;
    int m0 = blockIdx.y * BM;
    int n0 = blockIdx.x * BN;

    int rowL = tid >> 2;         // 0..63
    int colL = (tid & 3) * 4;    // 0,4,8,12
    int tr = tid >> 4;           // 0..15
    int tc = tid & 15;           // 0..15

    float acc[8][8];
#pragma unroll
    for (int i = 0; i < 8; i++)
#pragma unroll
        for (int j = 0; j < 8; j++) acc[i][j] = 0.f;

    for (int k0 = 0; k0 < K; k0 += BK) {
#pragma unroll
        for (int r = 0; r < 2; r++) {
            int row = rowL + r * 64;
            float4 va = *(const float4*)(A + (size_t)(m0 + row) * K + k0 + colL);
            As[colL + 0][row] = va.x; As[colL + 1][row] = va.y;
            As[colL + 2][row] = va.z; As[colL + 3][row] = va.w;
            float4 vb = *(const float4*)(W + (size_t)(n0 + row) * K + k0 + colL);
            Bs[colL + 0][row] = vb.x; Bs[colL + 1][row] = vb.y;
            Bs[colL + 2][row] = vb.z; Bs[colL + 3][row] = vb.w;
        }
        __syncthreads();
#pragma unroll
        for (int kk = 0; kk < BK; kk++) {
            float rm[8], rn[8];
#pragma unroll
            for (int i = 0; i < 8; i++) rm[i] = As[kk][tr * 8 + i];
#pragma unroll
            for (int j = 0; j < 8; j++) rn[j] = Bs[kk][tc * 8 + j];
#pragma unroll
            for (int i = 0; i < 8; i++)
#pragma unroll
                for (int j = 0; j < 8; j++)
                    acc[i][j] += rm[i] * rn[j];
        }
        __syncthreads();
    }

#pragma unroll
    for (int i = 0; i < 8; i++) {
        float* crow = C + (size_t)(m0 + tr * 8 + i) * N + n0 + tc * 8;
        float4 v0; v0.x = acc[i][0]; v0.y = acc[i][1]; v0.z = acc[i][2]; v0.w = acc[i][3];
        float4 v1; v1.x = acc[i][4]; v1.y = acc[i][5]; v1.z = acc[i][6]; v1.w = acc[i][7];
        *(float4*)(crow) = v0;
        *(float4*)(crow + 4) = v1;
    }
}

// ---------------- RoPE (in place), layout [b,s,nh,HD] --------------------------
__global__ void rope_kernel(float* __restrict__ x, int nheads, int total)
{
    int idx = blockIdx.x * blockDim.x + threadIdx.x;
    if (idx >= total) return;
    int j = idx & 63;                 // 0..63 (freq index)
    int rem = idx >> 6;
    int h = rem % nheads;
    int bs = rem / nheads;            // 0..MROWS-1
    int s = bs % SS;

    // inv_freq = 10000^(-j/64), fp32 like the reference
    float inv = expf(-(float)j * (logf(10000.0f) / 64.0f));
    float ang = (float)s * inv;
    float c = cosf(ang), sn = sinf(ang);

    float* p = x + ((size_t)bs * nheads + h) * HD;
    float x1 = p[j], x2 = p[j + 64];
    p[j]      = x1 * c - x2 * sn;
    p[j + 64] = x2 * c + x1 * sn;
}

// ---------------- Flash attention (causal, GQA n_rep=4) ------------------------
#define FBM 64
#define FBN 64
#define QP 129      /* pitch for Qs/Ks/Vs rows of 128 */
#define PP 65       /* pitch for Ps rows of 64 */

__global__ __launch_bounds__(256) void flash_kernel(
    const float* __restrict__ Q, const float* __restrict__ K,
    const float* __restrict__ V, float* __restrict__ Aout)
{
    extern __shared__ float sm[];
    float* Qs   = sm;                    // 64*129
    float* Ks   = Qs + FBM * QP;         // 64*129
    float* Vs   = Ks + FBN * QP;         // 64*129
    float* Ps   = Vs + FBN * QP;         // 64*65
    float* part = Ps + FBM * PP;         // 16*64
    float* m_s  = part + 16 * 64;        // 64
    float* l_s  = m_s + 64;              // 64
    float* al_s = l_s + 64;              // 64

    int tid = threadIdx.x;
    int qt = blockIdx.x;        // q tile 0..31
    int h  = blockIdx.y;        // head
    int b  = blockIdx.z;
    int kvh = h >> 2;           // n_rep = NH/NKV = 4
    int q0 = qt * FBM;

    const float scale = 0.08838834764831845f; // 1/sqrt(128)

    // Load + pre-scale Q tile
    for (int e = tid; e < FBM * HD; e += 256) {
        int r = e >> 7, d = e & 127;
        Qs[r * QP + d] = Q[(((size_t)b * SS + q0 + r) * NH + h) * HD + d] * scale;
    }
    if (tid < 64) { m_s[tid] = -INFINITY; l_s[tid] = 0.f; }

    int tr = tid >> 4, tc = tid & 15;
    float o[4][8];
#pragma unroll
    for (int i = 0; i < 4; i++)
#pragma unroll
        for (int j = 0; j < 8; j++) o[i][j] = 0.f;

    for (int kt = 0; kt <= qt; kt++) {
        __syncthreads();   // protect Ks/Vs/Ps reuse + init visibility
        int k0 = kt * FBN;
        for (int e = tid; e < FBN * HD; e += 256) {
            int r = e >> 7, d = e & 127;
            size_t gi = (((size_t)b * SS + k0 + r) * NKV + kvh) * HD + d;
            Ks[r * QP + d] = K[gi];
            Vs[r * QP + d] = V[gi];
        }
        __syncthreads();

        // S = Qs * Ks^T  (rows tr*4+i, cols tc*4+j)
        float sv[4][4];
#pragma unroll
        for (int i = 0; i < 4; i++)
#pragma unroll
            for (int j = 0; j < 4; j++) sv[i][j] = 0.f;
        for (int d = 0; d < HD; d++) {
            float rq[4], rk[4];
#pragma unroll
            for (int i = 0; i < 4; i++) rq[i] = Qs[(tr * 4 + i) * QP + d];
#pragma unroll
            for (int j = 0; j < 4; j++) rk[j] = Ks[(tc * 4 + j) * QP + d];
#pragma unroll
            for (int i = 0; i < 4; i++)
#pragma unroll
                for (int j = 0; j < 4; j++)
                    sv[i][j] += rq[i] * rk[j];
        }
        if (kt == qt) {
#pragma unroll
            for (int i = 0; i < 4; i++)
#pragma unroll
                for (int j = 0; j < 4; j++)
                    if (tc * 4 + j > tr * 4 + i) sv[i][j] = -INFINITY;
        }

        // partial row max
#pragma unroll
        for (int i = 0; i < 4; i++) {
            float mx = fmaxf(fmaxf(sv[i][0], sv[i][1]), fmaxf(sv[i][2], sv[i][3]));
            part[tc * 64 + tr * 4 + i] = mx;
        }
        __syncthreads();
        if (tid < 64) {
            float mx = part[tid];
            for (int c = 1; c < 16; c++) mx = fmaxf(mx, part[c * 64 + tid]);
            float mo = m_s[tid];
            float mn = fmaxf(mo, mx);
            m_s[tid] = mn;
            al_s[tid] = expf(mo - mn);   // 0 when mo == -inf
        }
        __syncthreads();

        // P = exp(S - m), partial row sums
#pragma unroll
        for (int i = 0; i < 4; i++) {
            float mn = m_s[tr * 4 + i];
            float p0 = expf(sv[i][0] - mn);
            float p1 = expf(sv[i][1] - mn);
            float p2 = expf(sv[i][2] - mn);
            float p3 = expf(sv[i][3] - mn);
            float* prow = Ps + (tr * 4 + i) * PP + tc * 4;
            prow[0] = p0; prow[1] = p1; prow[2] = p2; prow[3] = p3;
            part[tc * 64 + tr * 4 + i] = p0 + p1 + p2 + p3;
        }
        __syncthreads();
        if (tid < 64) {
            float s = 0.f;
            for (int c = 0; c < 16; c++) s += part[c * 64 + tid];
            l_s[tid] = l_s[tid] * al_s[tid] + s;
        }

        // rescale O, then O += P @ V
#pragma unroll
        for (int i = 0; i < 4; i++) {
            float a = al_s[tr * 4 + i];
#pragma unroll
            for (int j = 0; j < 8; j++) o[i][j] *= a;
        }
        for (int kk = 0; kk < FBN; kk++) {
            float rp[4], rv[8];
#pragma unroll
            for (int i = 0; i < 4; i++) rp[i] = Ps[(tr * 4 + i) * PP + kk];
#pragma unroll
            for (int j = 0; j < 8; j++) rv[j] = Vs[kk * QP + tc * 8 + j];
#pragma unroll
            for (int i = 0; i < 4; i++)
#pragma unroll
                for (int j = 0; j < 8; j++)
                    o[i][j] += rp[i] * rv[j];
        }
    }
    __syncthreads();   // l_s final values visible to all

#pragma unroll
    for (int i = 0; i < 4; i++) {
        float inv = 1.0f / l_s[tr * 4 + i];
        int s = q0 + tr * 4 + i;
        float* arow = Aout + (((size_t)b * SS + s) * NH + h) * HD + tc * 8;
#pragma unroll
        for (int j = 0; j < 8; j++) arow[j] = o[i][j] * inv;
    }
}

// ---------------- launch --------------------------------------------------------
extern "C" void kernel_launch(void* const* d_in, const int* in_sizes, int n_in,
                              void* d_out, int out_size)
{
    const float* x  = (const float*)d_in[0];
    const float* wq = (const float*)d_in[1];
    const float* wk = (const float*)d_in[2];
    const float* wv = (const float*)d_in[3];
    const float* wo = (const float*)d_in[4];
    float* out = (float*)d_out;

    float *Qp, *Kp, *Vp, *Ap;
    cudaGetSymbolAddress((void**)&Qp, g_Q);
    cudaGetSymbolAddress((void**)&Kp, g_K);
    cudaGetSymbolAddress((void**)&Vp, g_V);
    cudaGetSymbolAddress((void**)&Ap, g_A);

    // Projections
    sgemm_nt<<<dim3((NH * HD) / 128, MROWS / 128), 256>>>(x, wq, Qp, MROWS, NH * HD, HIDDEN);
    sgemm_nt<<<dim3((NKV * HD) / 128, MROWS / 128), 256>>>(x, wk, Kp, MROWS, NKV * HD, HIDDEN);
    sgemm_nt<<<dim3((NKV * HD) / 128, MROWS / 128), 256>>>(x, wv, Vp, MROWS, NKV * HD, HIDDEN);

    // RoPE
    int nq = MROWS * NH * 64;
    rope_kernel<<<(nq + 255) / 256, 256>>>(Qp, NH, nq);
    int nk = MROWS * NKV * 64;
    rope_kernel<<<(nk + 255) / 256, 256>>>(Kp, NKV, nk);

    // Flash attention
    int smem = (3 * FBM * QP + FBM * PP + 16 * 64 + 3 * 64) * (int)sizeof(float);
    cudaFuncSetAttribute(flash_kernel, cudaFuncAttributeMaxDynamicSharedMemorySize, smem);
    flash_kernel<<<dim3(SS / FBM, NH, BB), 256, smem>>>(Qp, Kp, Vp, Ap);

    // Output projection
    sgemm_nt<<<dim3(HIDDEN / 128, MROWS / 128), 256>>>(Ap, wo, out, MROWS, HIDDEN, HIDDEN);
}

// round 4
// speedup vs baseline: 1.5868x; 1.5868x over previous
#include <cuda_runtime.h>
#include <math.h>
#include <stdint.h>

#define HIDDEN 4096
#define NH 32
#define NKV 8
#define HD 128
#define BB 2
#define SS 2048
#define MROWS (BB*SS)   /* 4096 */

// ---------------- scratch -----------------------------------------------------
__device__ float g_Q[(size_t)MROWS * NH * HD];
__device__ float g_K[(size_t)MROWS * NKV * HD];
__device__ float g_V[(size_t)MROWS * NKV * HD];
__device__ float g_A[(size_t)MROWS * NH * HD];

__device__ __forceinline__ uint32_t f2tf32(float f) {
    uint32_t r; asm("cvt.rna.tf32.f32 %0, %1;" : "=r"(r) : "f"(f)); return r;
}

__device__ __forceinline__ void mma16n8k8(float* d, const uint32_t* a,
                                          uint32_t b0, uint32_t b1) {
    asm volatile(
        "mma.sync.aligned.m16n8k8.row.col.f32.tf32.tf32.f32 "
        "{%0,%1,%2,%3}, {%4,%5,%6,%7}, {%8,%9}, {%0,%1,%2,%3};"
        : "+f"(d[0]), "+f"(d[1]), "+f"(d[2]), "+f"(d[3])
        : "r"(a[0]), "r"(a[1]), "r"(a[2]), "r"(a[3]), "r"(b0), "r"(b1));
}

// ---------------- TF32 mma.sync GEMM: C[M,N] = A[M,K] * W[N,K]^T ---------------
// block tile 128x256 (8 warps of 64x64), BK=16, double-buffered smem,
// register prefetch. smem rows padded to 20 words (conflict-free frag loads).
#define BM 128
#define BN 256
#define BKC 16
#define APAD 20
#define BPAD 20
#define ASTRIDE (BM * APAD)             /* 2560 words per A stage */
#define BSTRIDE (BN * BPAD)             /* 5120 words per B stage */
#define GM_SMEM ((2 * ASTRIDE + 2 * BSTRIDE) * 4)   /* 61440 B */

__global__ __launch_bounds__(256, 1) void gemm_mma(
    const float* __restrict__ A, const float* __restrict__ W,
    float* __restrict__ C, int M, int N, int K)
{
    extern __shared__ float sm[];
    float* Asm = sm;                       // 2 stages
    float* Bsm = sm + 2 * ASTRIDE;         // 2 stages

    int tid = threadIdx.x;
    int lane = tid & 31, wid = tid >> 5;
    int wm = wid & 1, wn = wid >> 1;       // 2 x 4 warps
    int g = lane >> 2, tg = lane & 3;
    int m0 = blockIdx.y * BM;
    int n0 = blockIdx.x * BN;

    // staging assignment
    int arow = tid >> 1;                   // 0..127
    int acol = (tid & 1) * 8;              // 0 or 8
    int brow = tid;                        // 0..255

    float acc[4][8][4];
#pragma unroll
    for (int mf = 0; mf < 4; mf++)
#pragma unroll
        for (int nf = 0; nf < 8; nf++)
#pragma unroll
            for (int i = 0; i < 4; i++) acc[mf][nf][i] = 0.f;

    uint32_t pa[8], pb[16];
    const int NC = K / BKC;

    // prefetch lambda-free (macros via code)
#define LOAD_REGS(c) do { \
        int _k0 = (c) * BKC; \
        const float4* _as = (const float4*)(A + (size_t)(m0 + arow) * K + _k0 + acol); \
        _Pragma("unroll") \
        for (int _i = 0; _i < 2; _i++) { \
            float4 v = _as[_i]; \
            pa[_i*4+0] = f2tf32(v.x); pa[_i*4+1] = f2tf32(v.y); \
            pa[_i*4+2] = f2tf32(v.z); pa[_i*4+3] = f2tf32(v.w); \
        } \
        const float4* _bs = (const float4*)(W + (size_t)(n0 + brow) * K + _k0); \
        _Pragma("unroll") \
        for (int _i = 0; _i < 4; _i++) { \
            float4 v = _bs[_i]; \
            pb[_i*4+0] = f2tf32(v.x); pb[_i*4+1] = f2tf32(v.y); \
            pb[_i*4+2] = f2tf32(v.z); pb[_i*4+3] = f2tf32(v.w); \
        } \
    } while (0)

#define STORE_STAGE(buf) do { \
        uint32_t* _ad = (uint32_t*)(Asm + (buf) * ASTRIDE + arow * APAD + acol); \
        *(uint4*)(_ad)     = make_uint4(pa[0], pa[1], pa[2], pa[3]); \
        *(uint4*)(_ad + 4) = make_uint4(pa[4], pa[5], pa[6], pa[7]); \
        uint32_t* _bd = (uint32_t*)(Bsm + (buf) * BSTRIDE + brow * BPAD); \
        _Pragma("unroll") \
        for (int _i = 0; _i < 4; _i++) \
            *(uint4*)(_bd + _i * 4) = make_uint4(pb[_i*4], pb[_i*4+1], pb[_i*4+2], pb[_i*4+3]); \
    } while (0)

    LOAD_REGS(0);
    STORE_STAGE(0);
    __syncthreads();

    for (int c = 0; c < NC; c++) {
        int buf = c & 1;
        if (c + 1 < NC) LOAD_REGS(c + 1);

        const float* ap = Asm + buf * ASTRIDE;
        const float* bp = Bsm + buf * BSTRIDE;
#pragma unroll
        for (int kk = 0; kk < 2; kk++) {
            int kb = kk * 8;
            uint32_t afr[4][4];
#pragma unroll
            for (int mf = 0; mf < 4; mf++) {
                int r = wm * 64 + mf * 16 + g;
                afr[mf][0] = __float_as_uint(ap[r * APAD + kb + tg]);
                afr[mf][1] = __float_as_uint(ap[(r + 8) * APAD + kb + tg]);
                afr[mf][2] = __float_as_uint(ap[r * APAD + kb + tg + 4]);
                afr[mf][3] = __float_as_uint(ap[(r + 8) * APAD + kb + tg + 4]);
            }
#pragma unroll
            for (int nf = 0; nf < 8; nf++) {
                int n = wn * 64 + nf * 8 + g;
                uint32_t b0 = __float_as_uint(bp[n * BPAD + kb + tg]);
                uint32_t b1 = __float_as_uint(bp[n * BPAD + kb + tg + 4]);
#pragma unroll
                for (int mf = 0; mf < 4; mf++)
                    mma16n8k8(acc[mf][nf], afr[mf], b0, b1);
            }
        }
        if (c + 1 < NC) STORE_STAGE((c + 1) & 1);
        __syncthreads();
    }

    // epilogue
#pragma unroll
    for (int mf = 0; mf < 4; mf++) {
        int r = m0 + wm * 64 + mf * 16 + g;
#pragma unroll
        for (int nf = 0; nf < 8; nf++) {
            int col = n0 + wn * 64 + nf * 8 + 2 * tg;
            float2 v0; v0.x = acc[mf][nf][0]; v0.y = acc[mf][nf][1];
            float2 v1; v1.x = acc[mf][nf][2]; v1.y = acc[mf][nf][3];
            *(float2*)(C + (size_t)r * N + col) = v0;
            *(float2*)(C + (size_t)(r + 8) * N + col) = v1;
        }
    }
}

// ---------------- RoPE (in place), layout [b,s,nh,HD] --------------------------
__global__ void rope_kernel(float* __restrict__ x, int nheads, int total)
{
    int idx = blockIdx.x * blockDim.x + threadIdx.x;
    if (idx >= total) return;
    int j = idx & 63;
    int rem = idx >> 6;
    int h = rem % nheads;
    int bs = rem / nheads;
    int s = bs % SS;

    float inv = expf(-(float)j * (logf(10000.0f) / 64.0f));
    float ang = (float)s * inv;
    float c = cosf(ang), sn = sinf(ang);

    float* p = x + ((size_t)bs * nheads + h) * HD;
    float x1 = p[j], x2 = p[j + 64];
    p[j]      = x1 * c - x2 * sn;
    p[j + 64] = x2 * c + x1 * sn;
}

// ---------------- Flash attention (causal, GQA n_rep=4) ------------------------
#define FBM 64
#define FBN 64
#define QP 129
#define PP 65

__global__ __launch_bounds__(256) void flash_kernel(
    const float* __restrict__ Q, const float* __restrict__ K,
    const float* __restrict__ V, float* __restrict__ Aout)
{
    extern __shared__ float sm[];
    float* Qs   = sm;
    float* Ks   = Qs + FBM * QP;
    float* Vs   = Ks + FBN * QP;
    float* Ps   = Vs + FBN * QP;
    float* part = Ps + FBM * PP;
    float* m_s  = part + 16 * 64;
    float* l_s  = m_s + 64;
    float* al_s = l_s + 64;

    int tid = threadIdx.x;
    int qt = blockIdx.x;
    int h  = blockIdx.y;
    int b  = blockIdx.z;
    int kvh = h >> 2;
    int q0 = qt * FBM;

    const float scale = 0.08838834764831845f;

    for (int e = tid; e < FBM * HD; e += 256) {
        int r = e >> 7, d = e & 127;
        Qs[r * QP + d] = Q[(((size_t)b * SS + q0 + r) * NH + h) * HD + d] * scale;
    }
    if (tid < 64) { m_s[tid] = -INFINITY; l_s[tid] = 0.f; }

    int tr = tid >> 4, tc = tid & 15;
    float o[4][8];
#pragma unroll
    for (int i = 0; i < 4; i++)
#pragma unroll
        for (int j = 0; j < 8; j++) o[i][j] = 0.f;

    for (int kt = 0; kt <= qt; kt++) {
        __syncthreads();
        int k0 = kt * FBN;
        for (int e = tid; e < FBN * HD; e += 256) {
            int r = e >> 7, d = e & 127;
            size_t gi = (((size_t)b * SS + k0 + r) * NKV + kvh) * HD + d;
            Ks[r * QP + d] = K[gi];
            Vs[r * QP + d] = V[gi];
        }
        __syncthreads();

        float sv[4][4];
#pragma unroll
        for (int i = 0; i < 4; i++)
#pragma unroll
            for (int j = 0; j < 4; j++) sv[i][j] = 0.f;
        for (int d = 0; d < HD; d++) {
            float rq[4], rk[4];
#pragma unroll
            for (int i = 0; i < 4; i++) rq[i] = Qs[(tr * 4 + i) * QP + d];
#pragma unroll
            for (int j = 0; j < 4; j++) rk[j] = Ks[(tc * 4 + j) * QP + d];
#pragma unroll
            for (int i = 0; i < 4; i++)
#pragma unroll
                for (int j = 0; j < 4; j++)
                    sv[i][j] += rq[i] * rk[j];
        }
        if (kt == qt) {
#pragma unroll
            for (int i = 0; i < 4; i++)
#pragma unroll
                for (int j = 0; j < 4; j++)
                    if (tc * 4 + j > tr * 4 + i) sv[i][j] = -INFINITY;
        }

#pragma unroll
        for (int i = 0; i < 4; i++) {
            float mx = fmaxf(fmaxf(sv[i][0], sv[i][1]), fmaxf(sv[i][2], sv[i][3]));
            part[tc * 64 + tr * 4 + i] = mx;
        }
        __syncthreads();
        if (tid < 64) {
            float mx = part[tid];
            for (int c = 1; c < 16; c++) mx = fmaxf(mx, part[c * 64 + tid]);
            float mo = m_s[tid];
            float mn = fmaxf(mo, mx);
            m_s[tid] = mn;
            al_s[tid] = expf(mo - mn);
        }
        __syncthreads();

#pragma unroll
        for (int i = 0; i < 4; i++) {
            float mn = m_s[tr * 4 + i];
            float p0 = expf(sv[i][0] - mn);
            float p1 = expf(sv[i][1] - mn);
            float p2 = expf(sv[i][2] - mn);
            float p3 = expf(sv[i][3] - mn);
            float* prow = Ps + (tr * 4 + i) * PP + tc * 4;
            prow[0] = p0; prow[1] = p1; prow[2] = p2; prow[3] = p3;
            part[tc * 64 + tr * 4 + i] = p0 + p1 + p2 + p3;
        }
        __syncthreads();
        if (tid < 64) {
            float s = 0.f;
            for (int c = 0; c < 16; c++) s += part[c * 64 + tid];
            l_s[tid] = l_s[tid] * al_s[tid] + s;
        }

#pragma unroll
        for (int i = 0; i < 4; i++) {
            float a = al_s[tr * 4 + i];
#pragma unroll
            for (int j = 0; j < 8; j++) o[i][j] *= a;
        }
        for (int kk = 0; kk < FBN; kk++) {
            float rp[4], rv[8];
#pragma unroll
            for (int i = 0; i < 4; i++) rp[i] = Ps[(tr * 4 + i) * PP + kk];
#pragma unroll
            for (int j = 0; j < 8; j++) rv[j] = Vs[kk * QP + tc * 8 + j];
#pragma unroll
            for (int i = 0; i < 4; i++)
#pragma unroll
                for (int j = 0; j < 8; j++)
                    o[i][j] += rp[i] * rv[j];
        }
    }
    __syncthreads();

#pragma unroll
    for (int i = 0; i < 4; i++) {
        float inv = 1.0f / l_s[tr * 4 + i];
        int s = q0 + tr * 4 + i;
        float* arow = Aout + (((size_t)b * SS + s) * NH + h) * HD + tc * 8;
#pragma unroll
        for (int j = 0; j < 8; j++) arow[j] = o[i][j] * inv;
    }
}

// ---------------- launch --------------------------------------------------------
extern "C" void kernel_launch(void* const* d_in, const int* in_sizes, int n_in,
                              void* d_out, int out_size)
{
    const float* x  = (const float*)d_in[0];
    const float* wq = (const float*)d_in[1];
    const float* wk = (const float*)d_in[2];
    const float* wv = (const float*)d_in[3];
    const float* wo = (const float*)d_in[4];
    float* out = (float*)d_out;

    float *Qp, *Kp, *Vp, *Ap;
    cudaGetSymbolAddress((void**)&Qp, g_Q);
    cudaGetSymbolAddress((void**)&Kp, g_K);
    cudaGetSymbolAddress((void**)&Vp, g_V);
    cudaGetSymbolAddress((void**)&Ap, g_A);

    cudaFuncSetAttribute(gemm_mma, cudaFuncAttributeMaxDynamicSharedMemorySize, GM_SMEM);

    // Projections (TF32 tensor cores via mma.sync)
    gemm_mma<<<dim3((NH * HD) / BN, MROWS / BM), 256, GM_SMEM>>>(x, wq, Qp, MROWS, NH * HD, HIDDEN);
    gemm_mma<<<dim3((NKV * HD) / BN, MROWS / BM), 256, GM_SMEM>>>(x, wk, Kp, MROWS, NKV * HD, HIDDEN);
    gemm_mma<<<dim3((NKV * HD) / BN, MROWS / BM), 256, GM_SMEM>>>(x, wv, Vp, MROWS, NKV * HD, HIDDEN);

    // RoPE
    int nq = MROWS * NH * 64;
    rope_kernel<<<(nq + 255) / 256, 256>>>(Qp, NH, nq);
    int nk = MROWS * NKV * 64;
    rope_kernel<<<(nk + 255) / 256, 256>>>(Kp, NKV, nk);

    // Flash attention (fp32)
    int smem = (3 * FBM * QP + FBM * PP + 16 * 64 + 3 * 64) * (int)sizeof(float);
    cudaFuncSetAttribute(flash_kernel, cudaFuncAttributeMaxDynamicSharedMemorySize, smem);
    flash_kernel<<<dim3(SS / FBM, NH, BB), 256, smem>>>(Qp, Kp, Vp, Ap);

    // Output projection
    gemm_mma<<<dim3(HIDDEN / BN, MROWS / BM), 256, GM_SMEM>>>(Ap, wo, out, MROWS, HIDDEN, HIDDEN);
}

// round 5
// speedup vs baseline: 2.2934x; 1.4453x over previous
#include <cuda_runtime.h>
#include <cuda_bf16.h>
#include <math.h>
#include <stdint.h>

#define HIDDEN 4096
#define NH 32
#define NKV 8
#define HD 128
#define BB 2
#define SS 2048
#define MROWS (BB*SS)   /* 4096 */

// ---------------- scratch -----------------------------------------------------
__device__ float g_Q[(size_t)MROWS * NH * HD];
__device__ float g_K[(size_t)MROWS * NKV * HD];
__device__ float g_V[(size_t)MROWS * NKV * HD];
__device__ float g_A[(size_t)MROWS * NH * HD];

__device__ __forceinline__ uint32_t f2tf32(float f) {
    uint32_t r; asm("cvt.rna.tf32.f32 %0, %1;" : "=r"(r) : "f"(f)); return r;
}

__device__ __forceinline__ void mma16n8k8(float* d, const uint32_t* a,
                                          uint32_t b0, uint32_t b1) {
    asm volatile(
        "mma.sync.aligned.m16n8k8.row.col.f32.tf32.tf32.f32 "
        "{%0,%1,%2,%3}, {%4,%5,%6,%7}, {%8,%9}, {%0,%1,%2,%3};"
        : "+f"(d[0]), "+f"(d[1]), "+f"(d[2]), "+f"(d[3])
        : "r"(a[0]), "r"(a[1]), "r"(a[2]), "r"(a[3]), "r"(b0), "r"(b1));
}

__device__ __forceinline__ void mma_bf16(float* d, const uint32_t* a,
                                         uint32_t b0, uint32_t b1) {
    asm volatile(
        "mma.sync.aligned.m16n8k16.row.col.f32.bf16.bf16.f32 "
        "{%0,%1,%2,%3}, {%4,%5,%6,%7}, {%8,%9}, {%0,%1,%2,%3};"
        : "+f"(d[0]), "+f"(d[1]), "+f"(d[2]), "+f"(d[3])
        : "r"(a[0]), "r"(a[1]), "r"(a[2]), "r"(a[3]), "r"(b0), "r"(b1));
}

// ---------------- TF32 mma.sync GEMM: C[M,N] = A[M,K] * W[N,K]^T ---------------
#define BM 128
#define BN 256
#define BKC 16
#define APAD 20
#define BPAD 20
#define ASTRIDE (BM * APAD)
#define BSTRIDE (BN * BPAD)
#define GM_SMEM ((2 * ASTRIDE + 2 * BSTRIDE) * 4)

__global__ __launch_bounds__(256, 1) void gemm_mma(
    const float* __restrict__ A, const float* __restrict__ W,
    float* __restrict__ C, int M, int N, int K)
{
    extern __shared__ float sm[];
    float* Asm = sm;
    float* Bsm = sm + 2 * ASTRIDE;

    int tid = threadIdx.x;
    int lane = tid & 31, wid = tid >> 5;
    int wm = wid & 1, wn = wid >> 1;
    int g = lane >> 2, tg = lane & 3;
    int m0 = blockIdx.y * BM;
    int n0 = blockIdx.x * BN;

    int arow = tid >> 1;
    int acol = (tid & 1) * 8;
    int brow = tid;

    float acc[4][8][4];
#pragma unroll
    for (int mf = 0; mf < 4; mf++)
#pragma unroll
        for (int nf = 0; nf < 8; nf++)
#pragma unroll
            for (int i = 0; i < 4; i++) acc[mf][nf][i] = 0.f;

    uint32_t pa[8], pb[16];
    const int NC = K / BKC;

#define LOAD_REGS(c) do { \
        int _k0 = (c) * BKC; \
        const float4* _as = (const float4*)(A + (size_t)(m0 + arow) * K + _k0 + acol); \
        _Pragma("unroll") \
        for (int _i = 0; _i < 2; _i++) { \
            float4 v = _as[_i]; \
            pa[_i*4+0] = f2tf32(v.x); pa[_i*4+1] = f2tf32(v.y); \
            pa[_i*4+2] = f2tf32(v.z); pa[_i*4+3] = f2tf32(v.w); \
        } \
        const float4* _bs = (const float4*)(W + (size_t)(n0 + brow) * K + _k0); \
        _Pragma("unroll") \
        for (int _i = 0; _i < 4; _i++) { \
            float4 v = _bs[_i]; \
            pb[_i*4+0] = f2tf32(v.x); pb[_i*4+1] = f2tf32(v.y); \
            pb[_i*4+2] = f2tf32(v.z); pb[_i*4+3] = f2tf32(v.w); \
        } \
    } while (0)

#define STORE_STAGE(buf) do { \
        uint32_t* _ad = (uint32_t*)(Asm + (buf) * ASTRIDE + arow * APAD + acol); \
        *(uint4*)(_ad)     = make_uint4(pa[0], pa[1], pa[2], pa[3]); \
        *(uint4*)(_ad + 4) = make_uint4(pa[4], pa[5], pa[6], pa[7]); \
        uint32_t* _bd = (uint32_t*)(Bsm + (buf) * BSTRIDE + brow * BPAD); \
        _Pragma("unroll") \
        for (int _i = 0; _i < 4; _i++) \
            *(uint4*)(_bd + _i * 4) = make_uint4(pb[_i*4], pb[_i*4+1], pb[_i*4+2], pb[_i*4+3]); \
    } while (0)

    LOAD_REGS(0);
    STORE_STAGE(0);
    __syncthreads();

    for (int c = 0; c < NC; c++) {
        int buf = c & 1;
        if (c + 1 < NC) LOAD_REGS(c + 1);

        const float* ap = Asm + buf * ASTRIDE;
        const float* bp = Bsm + buf * BSTRIDE;
#pragma unroll
        for (int kk = 0; kk < 2; kk++) {
            int kb = kk * 8;
            uint32_t afr[4][4];
#pragma unroll
            for (int mf = 0; mf < 4; mf++) {
                int r = wm * 64 + mf * 16 + g;
                afr[mf][0] = __float_as_uint(ap[r * APAD + kb + tg]);
                afr[mf][1] = __float_as_uint(ap[(r + 8) * APAD + kb + tg]);
                afr[mf][2] = __float_as_uint(ap[r * APAD + kb + tg + 4]);
                afr[mf][3] = __float_as_uint(ap[(r + 8) * APAD + kb + tg + 4]);
            }
#pragma unroll
            for (int nf = 0; nf < 8; nf++) {
                int n = wn * 64 + nf * 8 + g;
                uint32_t b0 = __float_as_uint(bp[n * BPAD + kb + tg]);
                uint32_t b1 = __float_as_uint(bp[n * BPAD + kb + tg + 4]);
#pragma unroll
                for (int mf = 0; mf < 4; mf++)
                    mma16n8k8(acc[mf][nf], afr[mf], b0, b1);
            }
        }
        if (c + 1 < NC) STORE_STAGE((c + 1) & 1);
        __syncthreads();
    }

#pragma unroll
    for (int mf = 0; mf < 4; mf++) {
        int r = m0 + wm * 64 + mf * 16 + g;
#pragma unroll
        for (int nf = 0; nf < 8; nf++) {
            int col = n0 + wn * 64 + nf * 8 + 2 * tg;
            float2 v0; v0.x = acc[mf][nf][0]; v0.y = acc[mf][nf][1];
            float2 v1; v1.x = acc[mf][nf][2]; v1.y = acc[mf][nf][3];
            *(float2*)(C + (size_t)r * N + col) = v0;
            *(float2*)(C + (size_t)(r + 8) * N + col) = v1;
        }
    }
}

// ---------------- RoPE (in place), layout [b,s,nh,HD] --------------------------
__global__ void rope_kernel(float* __restrict__ x, int nheads, int total)
{
    int idx = blockIdx.x * blockDim.x + threadIdx.x;
    if (idx >= total) return;
    int j = idx & 63;
    int rem = idx >> 6;
    int h = rem % nheads;
    int bs = rem / nheads;
    int s = bs % SS;

    float inv = expf(-(float)j * (logf(10000.0f) / 64.0f));
    float ang = (float)s * inv;
    float c = cosf(ang), sn = sinf(ang);

    float* p = x + ((size_t)bs * nheads + h) * HD;
    float x1 = p[j], x2 = p[j + 64];
    p[j]      = x1 * c - x2 * sn;
    p[j + 64] = x2 * c + x1 * sn;
}

// ---------------- Flash attention (bf16x2 tensor cores, causal GQA) ------------
// 256 thr = 8 warps; Q tile 128 rows (16/warp), KV tile 64.
#define QPITCH 136
#define VPITCH 72
#define OFF_QH 0
#define OFF_QL (OFF_QH + 128*QPITCH)
#define OFF_KH (OFF_QL + 128*QPITCH)
#define OFF_KL (OFF_KH + 64*QPITCH)
#define OFF_VH (OFF_KL + 64*QPITCH)
#define OFF_VL (OFF_VH + 128*VPITCH)
#define OFF_PH (OFF_VL + 128*VPITCH)
#define OFF_PL (OFF_PH + 128*VPITCH)
#define FLASH_SMEM ((OFF_PL + 128*VPITCH) * 2)

__device__ __forceinline__ void split_store(__nv_bfloat16* dh, __nv_bfloat16* dl,
                                            float x0, float x1) {
    __nv_bfloat16 h0 = __float2bfloat16(x0);
    __nv_bfloat16 h1 = __float2bfloat16(x1);
    __nv_bfloat162 hv; hv.x = h0; hv.y = h1;
    __nv_bfloat162 lv;
    lv.x = __float2bfloat16(x0 - __bfloat162float(h0));
    lv.y = __float2bfloat16(x1 - __bfloat162float(h1));
    *(__nv_bfloat162*)dh = hv;
    *(__nv_bfloat162*)dl = lv;
}

__global__ __launch_bounds__(256, 1) void flash_mma(
    const float* __restrict__ Q, const float* __restrict__ K,
    const float* __restrict__ V, float* __restrict__ Aout)
{
    extern __shared__ __nv_bfloat16 fs[];
    __nv_bfloat16* Qh = fs + OFF_QH;
    __nv_bfloat16* Ql = fs + OFF_QL;
    __nv_bfloat16* Kh = fs + OFF_KH;
    __nv_bfloat16* Kl = fs + OFF_KL;
    __nv_bfloat16* Vh = fs + OFF_VH;
    __nv_bfloat16* Vl = fs + OFF_VL;
    __nv_bfloat16* Ph = fs + OFF_PH;
    __nv_bfloat16* Pl = fs + OFF_PL;

    int tid = threadIdx.x, lane = tid & 31, wm = tid >> 5;
    int g = lane >> 2, tg = lane & 3;
    int qt = blockIdx.x, h = blockIdx.y, b = blockIdx.z;
    int kvh = h >> 2;
    int q0 = qt * 128;
    const float scale = 0.08838834764831845f;
    const float NEGINF = __int_as_float(0xff800000);

    // Q load + scale + split
    {
        int r = tid >> 1, c0 = (tid & 1) * 64;
        const float* src = Q + (((size_t)b * SS + q0 + r) * NH + h) * HD + c0;
        __nv_bfloat16* dh = Qh + r * QPITCH + c0;
        __nv_bfloat16* dl = Ql + r * QPITCH + c0;
#pragma unroll
        for (int i = 0; i < 16; i++) {
            float4 v = ((const float4*)src)[i];
            v.x *= scale; v.y *= scale; v.z *= scale; v.w *= scale;
            split_store(dh + 4 * i,     dl + 4 * i,     v.x, v.y);
            split_store(dh + 4 * i + 2, dl + 4 * i + 2, v.z, v.w);
        }
    }

    float accO[16][4];
#pragma unroll
    for (int nf = 0; nf < 16; nf++)
#pragma unroll
        for (int i = 0; i < 4; i++) accO[nf][i] = 0.f;
    float m0 = NEGINF, m1 = NEGINF, l0 = 0.f, l1 = 0.f;

    int nkt = 2 * (qt + 1);
    for (int kt = 0; kt < nkt; kt++) {
        __syncthreads();
        int k0g = kt * 64;
        // K tile load + split
        {
            int r = tid >> 2, c0 = (tid & 3) * 32;
            const float* src = K + (((size_t)b * SS + k0g + r) * NKV + kvh) * HD + c0;
            __nv_bfloat16* dh = Kh + r * QPITCH + c0;
            __nv_bfloat16* dl = Kl + r * QPITCH + c0;
#pragma unroll
            for (int i = 0; i < 8; i++) {
                float4 v = ((const float4*)src)[i];
                split_store(dh + 4 * i,     dl + 4 * i,     v.x, v.y);
                split_store(dh + 4 * i + 2, dl + 4 * i + 2, v.z, v.w);
            }
        }
        // V tile load + transpose + split (pair-swizzled: pair kp stored at kp^(d&7))
#pragma unroll
        for (int u = 0; u < 4; u++) {
            int uu = tid + u * 256;
            int p = uu & 31, cg = uu >> 5;      // key pair p, col group cg
            const float* s0 = V + (((size_t)b * SS + k0g + 2 * p) * NKV + kvh) * HD + cg * 4;
            float4 v0 = *(const float4*)s0;
            float4 v1 = *(const float4*)(s0 + NKV * HD);
            float a0[4] = {v0.x, v0.y, v0.z, v0.w};
            float a1[4] = {v1.x, v1.y, v1.z, v1.w};
#pragma unroll
            for (int j = 0; j < 4; j++) {
                int d = cg * 4 + j;
                int kp = p ^ (d & 7);
                split_store(Vh + d * VPITCH + 2 * kp, Vl + d * VPITCH + 2 * kp,
                            a0[j], a1[j]);
            }
        }
        __syncthreads();

        bool active = (q0 + wm * 16 + 15) >= k0g;
        if (active) {
            float S[8][4];
#pragma unroll
            for (int nf = 0; nf < 8; nf++)
#pragma unroll
                for (int i = 0; i < 4; i++) S[nf][i] = 0.f;

            // S = Q K^T  (bf16x2: hh + hl + lh)
#pragma unroll
            for (int kc = 0; kc < 8; kc++) {
                uint32_t ah[4], al[4];
                const __nv_bfloat16* qb = Qh + (wm * 16 + g) * QPITCH + kc * 16 + 2 * tg;
                ah[0] = *(const uint32_t*)(qb);
                ah[1] = *(const uint32_t*)(qb + 8 * QPITCH);
                ah[2] = *(const uint32_t*)(qb + 8);
                ah[3] = *(const uint32_t*)(qb + 8 * QPITCH + 8);
                const __nv_bfloat16* ql = Ql + (wm * 16 + g) * QPITCH + kc * 16 + 2 * tg;
                al[0] = *(const uint32_t*)(ql);
                al[1] = *(const uint32_t*)(ql + 8 * QPITCH);
                al[2] = *(const uint32_t*)(ql + 8);
                al[3] = *(const uint32_t*)(ql + 8 * QPITCH + 8);
#pragma unroll
                for (int nf = 0; nf < 8; nf++) {
                    const __nv_bfloat16* kb = Kh + (nf * 8 + g) * QPITCH + kc * 16 + 2 * tg;
                    uint32_t bh0 = *(const uint32_t*)(kb);
                    uint32_t bh1 = *(const uint32_t*)(kb + 8);
                    const __nv_bfloat16* kl = Kl + (nf * 8 + g) * QPITCH + kc * 16 + 2 * tg;
                    uint32_t bl0 = *(const uint32_t*)(kl);
                    uint32_t bl1 = *(const uint32_t*)(kl + 8);
                    mma_bf16(S[nf], ah, bh0, bh1);
                    mma_bf16(S[nf], ah, bl0, bl1);
                    mma_bf16(S[nf], al, bh0, bh1);
                }
            }
            // causal mask
            if (k0g + 63 > q0 + wm * 16) {
                int row0 = q0 + wm * 16 + g, row1 = row0 + 8;
#pragma unroll
                for (int nf = 0; nf < 8; nf++) {
                    int col = k0g + nf * 8 + 2 * tg;
                    if (col     > row0) S[nf][0] = NEGINF;
                    if (col + 1 > row0) S[nf][1] = NEGINF;
                    if (col     > row1) S[nf][2] = NEGINF;
                    if (col + 1 > row1) S[nf][3] = NEGINF;
                }
            }
            // row max
            float mx0 = NEGINF, mx1 = NEGINF;
#pragma unroll
            for (int nf = 0; nf < 8; nf++) {
                mx0 = fmaxf(mx0, fmaxf(S[nf][0], S[nf][1]));
                mx1 = fmaxf(mx1, fmaxf(S[nf][2], S[nf][3]));
            }
            mx0 = fmaxf(mx0, __shfl_xor_sync(0xffffffff, mx0, 1));
            mx0 = fmaxf(mx0, __shfl_xor_sync(0xffffffff, mx0, 2));
            mx1 = fmaxf(mx1, __shfl_xor_sync(0xffffffff, mx1, 1));
            mx1 = fmaxf(mx1, __shfl_xor_sync(0xffffffff, mx1, 2));
            float m0n = fmaxf(m0, mx0), m1n = fmaxf(m1, mx1);
            float al0 = __expf(m0 - m0n), al1 = __expf(m1 - m1n);
            m0 = m0n; m1 = m1n;

            float sum0 = 0.f, sum1 = 0.f;
            int pr0 = (wm * 16 + g) * VPITCH, pr1 = (wm * 16 + g + 8) * VPITCH;
#pragma unroll
            for (int nf = 0; nf < 8; nf++) {
                float p00 = __expf(S[nf][0] - m0);
                float p01 = __expf(S[nf][1] - m0);
                float p10 = __expf(S[nf][2] - m1);
                float p11 = __expf(S[nf][3] - m1);
                sum0 += p00 + p01;
                sum1 += p10 + p11;
                int co = nf * 8 + 2 * tg;
                split_store(Ph + pr0 + co, Pl + pr0 + co, p00, p01);
                split_store(Ph + pr1 + co, Pl + pr1 + co, p10, p11);
            }
            sum0 += __shfl_xor_sync(0xffffffff, sum0, 1);
            sum0 += __shfl_xor_sync(0xffffffff, sum0, 2);
            sum1 += __shfl_xor_sync(0xffffffff, sum1, 1);
            sum1 += __shfl_xor_sync(0xffffffff, sum1, 2);
            l0 = l0 * al0 + sum0;
            l1 = l1 * al1 + sum1;
#pragma unroll
            for (int nf = 0; nf < 16; nf++) {
                accO[nf][0] *= al0; accO[nf][1] *= al0;
                accO[nf][2] *= al1; accO[nf][3] *= al1;
            }
            __syncwarp();
            // O += P V  (bf16x2)
#pragma unroll
            for (int kc = 0; kc < 4; kc++) {
                uint32_t pah[4], pal[4];
                const __nv_bfloat16* pb = Ph + (wm * 16 + g) * VPITCH + kc * 16 + 2 * tg;
                pah[0] = *(const uint32_t*)(pb);
                pah[1] = *(const uint32_t*)(pb + 8 * VPITCH);
                pah[2] = *(const uint32_t*)(pb + 8);
                pah[3] = *(const uint32_t*)(pb + 8 * VPITCH + 8);
                const __nv_bfloat16* pl = Pl + (wm * 16 + g) * VPITCH + kc * 16 + 2 * tg;
                pal[0] = *(const uint32_t*)(pl);
                pal[1] = *(const uint32_t*)(pl + 8 * VPITCH);
                pal[2] = *(const uint32_t*)(pl + 8);
                pal[3] = *(const uint32_t*)(pl + 8 * VPITCH + 8);
#pragma unroll
                for (int nf = 0; nf < 16; nf++) {
                    int n = nf * 8 + g;
                    int i0 = (8 * kc + tg) ^ (n & 7);
                    int i1 = (8 * kc + tg + 4) ^ (n & 7);
                    uint32_t bh0 = *(const uint32_t*)(Vh + n * VPITCH + 2 * i0);
                    uint32_t bh1 = *(const uint32_t*)(Vh + n * VPITCH + 2 * i1);
                    uint32_t bl0 = *(const uint32_t*)(Vl + n * VPITCH + 2 * i0);
                    uint32_t bl1 = *(const uint32_t*)(Vl + n * VPITCH + 2 * i1);
                    mma_bf16(accO[nf], pah, bh0, bh1);
                    mma_bf16(accO[nf], pah, bl0, bl1);
                    mma_bf16(accO[nf], pal, bh0, bh1);
                }
            }
        }
    }

    // epilogue
    float i0 = 1.0f / l0, i1 = 1.0f / l1;
    int r0 = q0 + wm * 16 + g;
    float* o0 = Aout + (((size_t)b * SS + r0) * NH + h) * HD;
    float* o1 = o0 + (size_t)8 * NH * HD;
#pragma unroll
    for (int nf = 0; nf < 16; nf++) {
        int d = nf * 8 + 2 * tg;
        float2 v0; v0.x = accO[nf][0] * i0; v0.y = accO[nf][1] * i0;
        float2 v1; v1.x = accO[nf][2] * i1; v1.y = accO[nf][3] * i1;
        *(float2*)(o0 + d) = v0;
        *(float2*)(o1 + d) = v1;
    }
}

// ---------------- launch --------------------------------------------------------
extern "C" void kernel_launch(void* const* d_in, const int* in_sizes, int n_in,
                              void* d_out, int out_size)
{
    const float* x  = (const float*)d_in[0];
    const float* wq = (const float*)d_in[1];
    const float* wk = (const float*)d_in[2];
    const float* wv = (const float*)d_in[3];
    const float* wo = (const float*)d_in[4];
    float* out = (float*)d_out;

    float *Qp, *Kp, *Vp, *Ap;
    cudaGetSymbolAddress((void**)&Qp, g_Q);
    cudaGetSymbolAddress((void**)&Kp, g_K);
    cudaGetSymbolAddress((void**)&Vp, g_V);
    cudaGetSymbolAddress((void**)&Ap, g_A);

    cudaFuncSetAttribute(gemm_mma, cudaFuncAttributeMaxDynamicSharedMemorySize, GM_SMEM);
    cudaFuncSetAttribute(flash_mma, cudaFuncAttributeMaxDynamicSharedMemorySize, FLASH_SMEM);

    // Projections (TF32 tensor cores)
    gemm_mma<<<dim3((NH * HD) / BN, MROWS / BM), 256, GM_SMEM>>>(x, wq, Qp, MROWS, NH * HD, HIDDEN);
    gemm_mma<<<dim3((NKV * HD) / BN, MROWS / BM), 256, GM_SMEM>>>(x, wk, Kp, MROWS, NKV * HD, HIDDEN);
    gemm_mma<<<dim3((NKV * HD) / BN, MROWS / BM), 256, GM_SMEM>>>(x, wv, Vp, MROWS, NKV * HD, HIDDEN);

    // RoPE
    int nq = MROWS * NH * 64;
    rope_kernel<<<(nq + 255) / 256, 256>>>(Qp, NH, nq);
    int nk = MROWS * NKV * 64;
    rope_kernel<<<(nk + 255) / 256, 256>>>(Kp, NKV, nk);

    // Flash attention (bf16x2 tensor cores)
    flash_mma<<<dim3(SS / 128, NH, BB), 256, FLASH_SMEM>>>(Qp, Kp, Vp, Ap);

    // Output projection
    gemm_mma<<<dim3(HIDDEN / BN, MROWS / BM), 256, GM_SMEM>>>(Ap, wo, out, MROWS, HIDDEN, HIDDEN);
}

// round 6
// speedup vs baseline: 2.5930x; 1.1307x over previous
#include <cuda_runtime.h>
#include <cuda_bf16.h>
#include <math.h>
#include <stdint.h>

#define HIDDEN 4096
#define NH 32
#define NKV 8
#define HD 128
#define BB 2
#define SS 2048
#define MROWS (BB*SS)   /* 4096 */

// ---------------- scratch -----------------------------------------------------
__device__ float g_Q[(size_t)MROWS * NH * HD];
__device__ float g_K[(size_t)MROWS * NKV * HD];
__device__ float g_V[(size_t)MROWS * NKV * HD];
__device__ float g_A[(size_t)MROWS * NH * HD];

__device__ __forceinline__ uint32_t f2tf32(float f) {
    uint32_t r; asm("cvt.rna.tf32.f32 %0, %1;" : "=r"(r) : "f"(f)); return r;
}

__device__ __forceinline__ void mma16n8k8(float* d, const uint32_t* a,
                                          uint32_t b0, uint32_t b1) {
    asm volatile(
        "mma.sync.aligned.m16n8k8.row.col.f32.tf32.tf32.f32 "
        "{%0,%1,%2,%3}, {%4,%5,%6,%7}, {%8,%9}, {%0,%1,%2,%3};"
        : "+f"(d[0]), "+f"(d[1]), "+f"(d[2]), "+f"(d[3])
        : "r"(a[0]), "r"(a[1]), "r"(a[2]), "r"(a[3]), "r"(b0), "r"(b1));
}

__device__ __forceinline__ void mma_bf16(float* d, const uint32_t* a,
                                         uint32_t b0, uint32_t b1) {
    asm volatile(
        "mma.sync.aligned.m16n8k16.row.col.f32.bf16.bf16.f32 "
        "{%0,%1,%2,%3}, {%4,%5,%6,%7}, {%8,%9}, {%0,%1,%2,%3};"
        : "+f"(d[0]), "+f"(d[1]), "+f"(d[2]), "+f"(d[3])
        : "r"(a[0]), "r"(a[1]), "r"(a[2]), "r"(a[3]), "r"(b0), "r"(b1));
}

__device__ __forceinline__ void cp16(float* smem_dst, const float* gsrc) {
    uint32_t d = (uint32_t)__cvta_generic_to_shared(smem_dst);
    asm volatile("cp.async.cg.shared.global [%0], [%1], 16;" :: "r"(d), "l"(gsrc));
}
#define CP_COMMIT() asm volatile("cp.async.commit_group;" ::: "memory")
#define CP_WAIT1()  asm volatile("cp.async.wait_group 1;" ::: "memory")

// ---------------- TF32 mma.sync GEMM: C[M,N] = A[M,K] * W[N,K]^T ---------------
// 128x256 tile, BK=16, 3-stage cp.async pipeline, cvt-on-fragment-load.
#define BM 128
#define BN 256
#define BKC 16
#define APAD 20
#define BPAD 20
#define ASTG (BM * APAD)          /* 2560 floats */
#define BSTG (BN * BPAD)          /* 5120 floats */
#define STG  (ASTG + BSTG)        /* 7680 floats per stage */
#define NSTAGE 3
#define GM_SMEM (NSTAGE * STG * 4)   /* 92160 B */

__global__ __launch_bounds__(256, 1) void gemm_mma(
    const float* __restrict__ A, const float* __restrict__ W,
    float* __restrict__ C, int M, int N, int K)
{
    extern __shared__ float sm[];

    int tid = threadIdx.x;
    int lane = tid & 31, wid = tid >> 5;
    int wm = wid & 1, wn = wid >> 1;
    int g = lane >> 2, tg = lane & 3;
    int m0 = blockIdx.y * BM;
    int n0 = blockIdx.x * BN;

    int arow = tid >> 1;
    int acol = (tid & 1) * 8;
    int brow = tid;

    const float* agsrc = A + (size_t)(m0 + arow) * K + acol;
    const float* bgsrc = W + (size_t)(n0 + brow) * K;

    float acc[4][8][4];
#pragma unroll
    for (int mf = 0; mf < 4; mf++)
#pragma unroll
        for (int nf = 0; nf < 8; nf++)
#pragma unroll
            for (int i = 0; i < 4; i++) acc[mf][nf][i] = 0.f;

    const int NC = K / BKC;

#define ISSUE_STAGE(c) do { \
        int _buf = (c) % NSTAGE; \
        float* _Ad = sm + _buf * STG + arow * APAD + acol; \
        float* _Bd = sm + _buf * STG + ASTG + brow * BPAD; \
        int _k0 = (c) * BKC; \
        cp16(_Ad,     agsrc + _k0); \
        cp16(_Ad + 4, agsrc + _k0 + 4); \
        cp16(_Bd,      bgsrc + _k0); \
        cp16(_Bd + 4,  bgsrc + _k0 + 4); \
        cp16(_Bd + 8,  bgsrc + _k0 + 8); \
        cp16(_Bd + 12, bgsrc + _k0 + 12); \
    } while (0)

    ISSUE_STAGE(0); CP_COMMIT();
    ISSUE_STAGE(1); CP_COMMIT();

    for (int c = 0; c < NC; c++) {
        CP_WAIT1();
        __syncthreads();
        if (c + 2 < NC) ISSUE_STAGE(c + 2);
        CP_COMMIT();

        int buf = c % NSTAGE;
        const float* ap = sm + buf * STG;
        const float* bp = sm + buf * STG + ASTG;
#pragma unroll
        for (int kk = 0; kk < 2; kk++) {
            int kb = kk * 8;
            uint32_t afr[4][4];
#pragma unroll
            for (int mf = 0; mf < 4; mf++) {
                int r = wm * 64 + mf * 16 + g;
                afr[mf][0] = f2tf32(ap[r * APAD + kb + tg]);
                afr[mf][1] = f2tf32(ap[(r + 8) * APAD + kb + tg]);
                afr[mf][2] = f2tf32(ap[r * APAD + kb + tg + 4]);
                afr[mf][3] = f2tf32(ap[(r + 8) * APAD + kb + tg + 4]);
            }
#pragma unroll
            for (int nf = 0; nf < 8; nf++) {
                int n = wn * 64 + nf * 8 + g;
                uint32_t b0 = f2tf32(bp[n * BPAD + kb + tg]);
                uint32_t b1 = f2tf32(bp[n * BPAD + kb + tg + 4]);
#pragma unroll
                for (int mf = 0; mf < 4; mf++)
                    mma16n8k8(acc[mf][nf], afr[mf], b0, b1);
            }
        }
        __syncthreads();
    }

#pragma unroll
    for (int mf = 0; mf < 4; mf++) {
        int r = m0 + wm * 64 + mf * 16 + g;
#pragma unroll
        for (int nf = 0; nf < 8; nf++) {
            int col = n0 + wn * 64 + nf * 8 + 2 * tg;
            float2 v0; v0.x = acc[mf][nf][0]; v0.y = acc[mf][nf][1];
            float2 v1; v1.x = acc[mf][nf][2]; v1.y = acc[mf][nf][3];
            *(float2*)(C + (size_t)r * N + col) = v0;
            *(float2*)(C + (size_t)(r + 8) * N + col) = v1;
        }
    }
}

// ---------------- RoPE (in place), layout [b,s,nh,HD] --------------------------
__global__ void rope_kernel(float* __restrict__ x, int nheads, int total)
{
    int idx = blockIdx.x * blockDim.x + threadIdx.x;
    if (idx >= total) return;
    int j = idx & 63;
    int rem = idx >> 6;
    int h = rem % nheads;
    int bs = rem / nheads;
    int s = bs % SS;

    float inv = expf(-(float)j * (logf(10000.0f) / 64.0f));
    float ang = (float)s * inv;
    float c = cosf(ang), sn = sinf(ang);

    float* p = x + ((size_t)bs * nheads + h) * HD;
    float x1 = p[j], x2 = p[j + 64];
    p[j]      = x1 * c - x2 * sn;
    p[j + 64] = x2 * c + x1 * sn;
}

// ---------------- Flash attention (bf16x2 tensor cores, causal GQA) ------------
#define QPITCH 136
#define VPITCH 72
#define OFF_QH 0
#define OFF_QL (OFF_QH + 128*QPITCH)
#define OFF_KH (OFF_QL + 128*QPITCH)
#define OFF_KL (OFF_KH + 64*QPITCH)
#define OFF_VH (OFF_KL + 64*QPITCH)
#define OFF_VL (OFF_VH + 128*VPITCH)
#define OFF_PH (OFF_VL + 128*VPITCH)
#define OFF_PL (OFF_PH + 128*VPITCH)
#define FLASH_SMEM ((OFF_PL + 128*VPITCH) * 2)

__device__ __forceinline__ void split_store(__nv_bfloat16* dh, __nv_bfloat16* dl,
                                            float x0, float x1) {
    __nv_bfloat16 h0 = __float2bfloat16(x0);
    __nv_bfloat16 h1 = __float2bfloat16(x1);
    __nv_bfloat162 hv; hv.x = h0; hv.y = h1;
    __nv_bfloat162 lv;
    lv.x = __float2bfloat16(x0 - __bfloat162float(h0));
    lv.y = __float2bfloat16(x1 - __bfloat162float(h1));
    *(__nv_bfloat162*)dh = hv;
    *(__nv_bfloat162*)dl = lv;
}

__global__ __launch_bounds__(256, 1) void flash_mma(
    const float* __restrict__ Q, const float* __restrict__ K,
    const float* __restrict__ V, float* __restrict__ Aout)
{
    extern __shared__ __nv_bfloat16 fs[];
    __nv_bfloat16* Qh = fs + OFF_QH;
    __nv_bfloat16* Ql = fs + OFF_QL;
    __nv_bfloat16* Kh = fs + OFF_KH;
    __nv_bfloat16* Kl = fs + OFF_KL;
    __nv_bfloat16* Vh = fs + OFF_VH;
    __nv_bfloat16* Vl = fs + OFF_VL;
    __nv_bfloat16* Ph = fs + OFF_PH;
    __nv_bfloat16* Pl = fs + OFF_PL;

    int tid = threadIdx.x, lane = tid & 31, wm = tid >> 5;
    int g = lane >> 2, tg = lane & 3;
    int qt = blockIdx.x, h = blockIdx.y, b = blockIdx.z;
    int kvh = h >> 2;
    int q0 = qt * 128;
    const float scale = 0.08838834764831845f;
    const float NEGINF = __int_as_float(0xff800000);

    {
        int r = tid >> 1, c0 = (tid & 1) * 64;
        const float* src = Q + (((size_t)b * SS + q0 + r) * NH + h) * HD + c0;
        __nv_bfloat16* dh = Qh + r * QPITCH + c0;
        __nv_bfloat16* dl = Ql + r * QPITCH + c0;
#pragma unroll
        for (int i = 0; i < 16; i++) {
            float4 v = ((const float4*)src)[i];
            v.x *= scale; v.y *= scale; v.z *= scale; v.w *= scale;
            split_store(dh + 4 * i,     dl + 4 * i,     v.x, v.y);
            split_store(dh + 4 * i + 2, dl + 4 * i + 2, v.z, v.w);
        }
    }

    float accO[16][4];
#pragma unroll
    for (int nf = 0; nf < 16; nf++)
#pragma unroll
        for (int i = 0; i < 4; i++) accO[nf][i] = 0.f;
    float m0 = NEGINF, m1 = NEGINF, l0 = 0.f, l1 = 0.f;

    int nkt = 2 * (qt + 1);
    for (int kt = 0; kt < nkt; kt++) {
        __syncthreads();
        int k0g = kt * 64;
        {
            int r = tid >> 2, c0 = (tid & 3) * 32;
            const float* src = K + (((size_t)b * SS + k0g + r) * NKV + kvh) * HD + c0;
            __nv_bfloat16* dh = Kh + r * QPITCH + c0;
            __nv_bfloat16* dl = Kl + r * QPITCH + c0;
#pragma unroll
            for (int i = 0; i < 8; i++) {
                float4 v = ((const float4*)src)[i];
                split_store(dh + 4 * i,     dl + 4 * i,     v.x, v.y);
                split_store(dh + 4 * i + 2, dl + 4 * i + 2, v.z, v.w);
            }
        }
#pragma unroll
        for (int u = 0; u < 4; u++) {
            int uu = tid + u * 256;
            int p = uu & 31, cg = uu >> 5;
            const float* s0 = V + (((size_t)b * SS + k0g + 2 * p) * NKV + kvh) * HD + cg * 4;
            float4 v0 = *(const float4*)s0;
            float4 v1 = *(const float4*)(s0 + NKV * HD);
            float a0[4] = {v0.x, v0.y, v0.z, v0.w};
            float a1[4] = {v1.x, v1.y, v1.z, v1.w};
#pragma unroll
            for (int j = 0; j < 4; j++) {
                int d = cg * 4 + j;
                int kp = p ^ (d & 7);
                split_store(Vh + d * VPITCH + 2 * kp, Vl + d * VPITCH + 2 * kp,
                            a0[j], a1[j]);
            }
        }
        __syncthreads();

        bool active = (q0 + wm * 16 + 15) >= k0g;
        if (active) {
            float S[8][4];
#pragma unroll
            for (int nf = 0; nf < 8; nf++)
#pragma unroll
                for (int i = 0; i < 4; i++) S[nf][i] = 0.f;

#pragma unroll
            for (int kc = 0; kc < 8; kc++) {
                uint32_t ah[4], al[4];
                const __nv_bfloat16* qb = Qh + (wm * 16 + g) * QPITCH + kc * 16 + 2 * tg;
                ah[0] = *(const uint32_t*)(qb);
                ah[1] = *(const uint32_t*)(qb + 8 * QPITCH);
                ah[2] = *(const uint32_t*)(qb + 8);
                ah[3] = *(const uint32_t*)(qb + 8 * QPITCH + 8);
                const __nv_bfloat16* ql = Ql + (wm * 16 + g) * QPITCH + kc * 16 + 2 * tg;
                al[0] = *(const uint32_t*)(ql);
                al[1] = *(const uint32_t*)(ql + 8 * QPITCH);
                al[2] = *(const uint32_t*)(ql + 8);
                al[3] = *(const uint32_t*)(ql + 8 * QPITCH + 8);
#pragma unroll
                for (int nf = 0; nf < 8; nf++) {
                    const __nv_bfloat16* kb = Kh + (nf * 8 + g) * QPITCH + kc * 16 + 2 * tg;
                    uint32_t bh0 = *(const uint32_t*)(kb);
                    uint32_t bh1 = *(const uint32_t*)(kb + 8);
                    const __nv_bfloat16* kl = Kl + (nf * 8 + g) * QPITCH + kc * 16 + 2 * tg;
                    uint32_t bl0 = *(const uint32_t*)(kl);
                    uint32_t bl1 = *(const uint32_t*)(kl + 8);
                    mma_bf16(S[nf], ah, bh0, bh1);
                    mma_bf16(S[nf], ah, bl0, bl1);
                    mma_bf16(S[nf], al, bh0, bh1);
                }
            }
            if (k0g + 63 > q0 + wm * 16) {
                int row0 = q0 + wm * 16 + g, row1 = row0 + 8;
#pragma unroll
                for (int nf = 0; nf < 8; nf++) {
                    int col = k0g + nf * 8 + 2 * tg;
                    if (col     > row0) S[nf][0] = NEGINF;
                    if (col + 1 > row0) S[nf][1] = NEGINF;
                    if (col     > row1) S[nf][2] = NEGINF;
                    if (col + 1 > row1) S[nf][3] = NEGINF;
                }
            }
            float mx0 = NEGINF, mx1 = NEGINF;
#pragma unroll
            for (int nf = 0; nf < 8; nf++) {
                mx0 = fmaxf(mx0, fmaxf(S[nf][0], S[nf][1]));
                mx1 = fmaxf(mx1, fmaxf(S[nf][2], S[nf][3]));
            }
            mx0 = fmaxf(mx0, __shfl_xor_sync(0xffffffff, mx0, 1));
            mx0 = fmaxf(mx0, __shfl_xor_sync(0xffffffff, mx0, 2));
            mx1 = fmaxf(mx1, __shfl_xor_sync(0xffffffff, mx1, 1));
            mx1 = fmaxf(mx1, __shfl_xor_sync(0xffffffff, mx1, 2));
            float m0n = fmaxf(m0, mx0), m1n = fmaxf(m1, mx1);
            float al0 = __expf(m0 - m0n), al1 = __expf(m1 - m1n);
            m0 = m0n; m1 = m1n;

            float sum0 = 0.f, sum1 = 0.f;
            int pr0 = (wm * 16 + g) * VPITCH, pr1 = (wm * 16 + g + 8) * VPITCH;
#pragma unroll
            for (int nf = 0; nf < 8; nf++) {
                float p00 = __expf(S[nf][0] - m0);
                float p01 = __expf(S[nf][1] - m0);
                float p10 = __expf(S[nf][2] - m1);
                float p11 = __expf(S[nf][3] - m1);
                sum0 += p00 + p01;
                sum1 += p10 + p11;
                int co = nf * 8 + 2 * tg;
                split_store(Ph + pr0 + co, Pl + pr0 + co, p00, p01);
                split_store(Ph + pr1 + co, Pl + pr1 + co, p10, p11);
            }
            sum0 += __shfl_xor_sync(0xffffffff, sum0, 1);
            sum0 += __shfl_xor_sync(0xffffffff, sum0, 2);
            sum1 += __shfl_xor_sync(0xffffffff, sum1, 1);
            sum1 += __shfl_xor_sync(0xffffffff, sum1, 2);
            l0 = l0 * al0 + sum0;
            l1 = l1 * al1 + sum1;
#pragma unroll
            for (int nf = 0; nf < 16; nf++) {
                accO[nf][0] *= al0; accO[nf][1] *= al0;
                accO[nf][2] *= al1; accO[nf][3] *= al1;
            }
            __syncwarp();
#pragma unroll
            for (int kc = 0; kc < 4; kc++) {
                uint32_t pah[4], pal[4];
                const __nv_bfloat16* pb = Ph + (wm * 16 + g) * VPITCH + kc * 16 + 2 * tg;
                pah[0] = *(const uint32_t*)(pb);
                pah[1] = *(const uint32_t*)(pb + 8 * VPITCH);
                pah[2] = *(const uint32_t*)(pb + 8);
                pah[3] = *(const uint32_t*)(pb + 8 * VPITCH + 8);
                const __nv_bfloat16* pl = Pl + (wm * 16 + g) * VPITCH + kc * 16 + 2 * tg;
                pal[0] = *(const uint32_t*)(pl);
                pal[1] = *(const uint32_t*)(pl + 8 * VPITCH);
                pal[2] = *(const uint32_t*)(pl + 8);
                pal[3] = *(const uint32_t*)(pl + 8 * VPITCH + 8);
#pragma unroll
                for (int nf = 0; nf < 16; nf++) {
                    int n = nf * 8 + g;
                    int i0 = (8 * kc + tg) ^ (n & 7);
                    int i1 = (8 * kc + tg + 4) ^ (n & 7);
                    uint32_t bh0 = *(const uint32_t*)(Vh + n * VPITCH + 2 * i0);
                    uint32_t bh1 = *(const uint32_t*)(Vh + n * VPITCH + 2 * i1);
                    uint32_t bl0 = *(const uint32_t*)(Vl + n * VPITCH + 2 * i0);
                    uint32_t bl1 = *(const uint32_t*)(Vl + n * VPITCH + 2 * i1);
                    mma_bf16(accO[nf], pah, bh0, bh1);
                    mma_bf16(accO[nf], pah, bl0, bl1);
                    mma_bf16(accO[nf], pal, bh0, bh1);
                }
            }
        }
    }

    float i0 = 1.0f / l0, i1 = 1.0f / l1;
    int r0 = q0 + wm * 16 + g;
    float* o0 = Aout + (((size_t)b * SS + r0) * NH + h) * HD;
    float* o1 = o0 + (size_t)8 * NH * HD;
#pragma unroll
    for (int nf = 0; nf < 16; nf++) {
        int d = nf * 8 + 2 * tg;
        float2 v0; v0.x = accO[nf][0] * i0; v0.y = accO[nf][1] * i0;
        float2 v1; v1.x = accO[nf][2] * i1; v1.y = accO[nf][3] * i1;
        *(float2*)(o0 + d) = v0;
        *(float2*)(o1 + d) = v1;
    }
}

// ---------------- launch --------------------------------------------------------
extern "C" void kernel_launch(void* const* d_in, const int* in_sizes, int n_in,
                              void* d_out, int out_size)
{
    const float* x  = (const float*)d_in[0];
    const float* wq = (const float*)d_in[1];
    const float* wk = (const float*)d_in[2];
    const float* wv = (const float*)d_in[3];
    const float* wo = (const float*)d_in[4];
    float* out = (float*)d_out;

    float *Qp, *Kp, *Vp, *Ap;
    cudaGetSymbolAddress((void**)&Qp, g_Q);
    cudaGetSymbolAddress((void**)&Kp, g_K);
    cudaGetSymbolAddress((void**)&Vp, g_V);
    cudaGetSymbolAddress((void**)&Ap, g_A);

    cudaFuncSetAttribute(gemm_mma, cudaFuncAttributeMaxDynamicSharedMemorySize, GM_SMEM);
    cudaFuncSetAttribute(flash_mma, cudaFuncAttributeMaxDynamicSharedMemorySize, FLASH_SMEM);

    // Projections (TF32 tensor cores, cp.async pipeline)
    gemm_mma<<<dim3((NH * HD) / BN, MROWS / BM), 256, GM_SMEM>>>(x, wq, Qp, MROWS, NH * HD, HIDDEN);
    gemm_mma<<<dim3((NKV * HD) / BN, MROWS / BM), 256, GM_SMEM>>>(x, wk, Kp, MROWS, NKV * HD, HIDDEN);
    gemm_mma<<<dim3((NKV * HD) / BN, MROWS / BM), 256, GM_SMEM>>>(x, wv, Vp, MROWS, NKV * HD, HIDDEN);

    // RoPE
    int nq = MROWS * NH * 64;
    rope_kernel<<<(nq + 255) / 256, 256>>>(Qp, NH, nq);
    int nk = MROWS * NKV * 64;
    rope_kernel<<<(nk + 255) / 256, 256>>>(Kp, NKV, nk);

    // Flash attention (bf16x2 tensor cores)
    flash_mma<<<dim3(SS / 128, NH, BB), 256, FLASH_SMEM>>>(Qp, Kp, Vp, Ap);

    // Output projection
    gemm_mma<<<dim3(HIDDEN / BN, MROWS / BM), 256, GM_SMEM>>>(Ap, wo, out, MROWS, HIDDEN, HIDDEN);
}

// round 7
// speedup vs baseline: 2.8163x; 1.0861x over previous
#include <cuda_runtime.h>
#include <cuda_bf16.h>
#include <math.h>
#include <stdint.h>

#define HIDDEN 4096
#define NH 32
#define NKV 8
#define HD 128
#define BB 2
#define SS 2048
#define MROWS (BB*SS)   /* 4096 */

// ---------------- scratch -----------------------------------------------------
__device__ float g_Q[(size_t)MROWS * NH * HD];
__device__ float g_K[(size_t)MROWS * NKV * HD];
__device__ float g_V[(size_t)MROWS * NKV * HD];
__device__ float g_A[(size_t)MROWS * NH * HD];
// packed (tf32 bits, mma-fragment-major)
__device__ uint32_t g_Xp [(size_t)MROWS * HIDDEN];       // x packed as A
__device__ uint32_t g_Wqp[(size_t)NH  * HD * HIDDEN];    // wq packed as B
__device__ uint32_t g_Wkp[(size_t)NKV * HD * HIDDEN];
__device__ uint32_t g_Wvp[(size_t)NKV * HD * HIDDEN];
__device__ uint32_t g_Wop[(size_t)HIDDEN * NH * HD];     // wo packed as B

__device__ __forceinline__ uint32_t f2tf32(float f) {
    uint32_t r; asm("cvt.rna.tf32.f32 %0, %1;" : "=r"(r) : "f"(f)); return r;
}

__device__ __forceinline__ void mma16n8k8(float* d, const uint32_t* a,
                                          uint32_t b0, uint32_t b1) {
    asm volatile(
        "mma.sync.aligned.m16n8k8.row.col.f32.tf32.tf32.f32 "
        "{%0,%1,%2,%3}, {%4,%5,%6,%7}, {%8,%9}, {%0,%1,%2,%3};"
        : "+f"(d[0]), "+f"(d[1]), "+f"(d[2]), "+f"(d[3])
        : "r"(a[0]), "r"(a[1]), "r"(a[2]), "r"(a[3]), "r"(b0), "r"(b1));
}

__device__ __forceinline__ void mma_bf16(float* d, const uint32_t* a,
                                         uint32_t b0, uint32_t b1) {
    asm volatile(
        "mma.sync.aligned.m16n8k16.row.col.f32.bf16.bf16.f32 "
        "{%0,%1,%2,%3}, {%4,%5,%6,%7}, {%8,%9}, {%0,%1,%2,%3};"
        : "+f"(d[0]), "+f"(d[1]), "+f"(d[2]), "+f"(d[3])
        : "r"(a[0]), "r"(a[1]), "r"(a[2]), "r"(a[3]), "r"(b0), "r"(b1));
}

// ---------------- packing kernels ---------------------------------------------
// A-pack: per 16x8 tile, lane (g=l>>2,tg=l&3) holds {a[g,tg], a[g+8,tg], a[g,tg+4], a[g+8,tg+4]}
__global__ __launch_bounds__(256) void pack_a(const float* __restrict__ X,
                                              uint32_t* __restrict__ Xp,
                                              int M, int K)
{
    int idx = blockIdx.x * 256 + threadIdx.x;
    int total = (M >> 4) * (K >> 3) * 32;
    if (idx >= total) return;
    int lane = idx & 31, t = idx >> 5;
    int KT = K >> 3;
    int kt = t % KT, mt = t / KT;
    int g = lane >> 2, tg = lane & 3;
    size_t r0 = (size_t)(mt * 16 + g) * K + kt * 8 + tg;
    uint4 v;
    v.x = f2tf32(X[r0]);
    v.y = f2tf32(X[r0 + (size_t)8 * K]);
    v.z = f2tf32(X[r0 + 4]);
    v.w = f2tf32(X[r0 + (size_t)8 * K + 4]);
    ((uint4*)Xp)[(size_t)t * 32 + lane] = v;
}

// B-pack: per 8x8 tile, lane (g,tg) holds {w[g,tg], w[g,tg+4]}
__global__ __launch_bounds__(256) void pack_b(const float* __restrict__ W,
                                              uint32_t* __restrict__ Wp,
                                              int N, int K)
{
    int idx = blockIdx.x * 256 + threadIdx.x;
    int total = (N >> 3) * (K >> 3) * 32;
    if (idx >= total) return;
    int lane = idx & 31, t = idx >> 5;
    int KT = K >> 3;
    int kt = t % KT, nt = t / KT;
    int g = lane >> 2, tg = lane & 3;
    size_t r0 = (size_t)(nt * 8 + g) * K + kt * 8 + tg;
    uint2 v;
    v.x = f2tf32(W[r0]);
    v.y = f2tf32(W[r0 + 4]);
    ((uint2*)Wp)[(size_t)t * 32 + lane] = v;
}

// ---------------- fragment-direct TF32 GEMM: C = A * W^T -----------------------
// 128x256 tile, 8 warps (2x4), NO smem. A: packed(u4/lane) or raw float.
template<int PACKED_A>
__global__ __launch_bounds__(256, 1) void gemm_fp(
    const float* __restrict__ Af, const uint32_t* __restrict__ Apk,
    const uint32_t* __restrict__ Bp, float* __restrict__ C,
    int M, int N, int K)
{
    int tid = threadIdx.x;
    int lane = tid & 31, wid = tid >> 5;
    int wm = wid & 1, wn = wid >> 1;
    int g = lane >> 2, tg = lane & 3;
    int m0 = blockIdx.y * 128;
    int n0 = blockIdx.x * 256;
    const int KT = K >> 3;

    const uint2* bP = (const uint2*)Bp + ((size_t)((n0 >> 3) + wn * 8) * KT) * 32 + lane;
    const size_t bStep = (size_t)KT * 32;   // per ntile, uint2 units

    const uint4* aP = 0;
    const float *a0p[4], *a1p[4];
    size_t aStep = 0;
    if (PACKED_A) {
        aP = (const uint4*)Apk + ((size_t)((m0 >> 4) + wm * 4) * KT) * 32 + lane;
        aStep = (size_t)KT * 32;            // per mtile, uint4 units
    } else {
#pragma unroll
        for (int mf = 0; mf < 4; mf++) {
            int r = m0 + wm * 64 + mf * 16 + g;
            a0p[mf] = Af + (size_t)r * K + tg;
            a1p[mf] = Af + (size_t)(r + 8) * K + tg;
        }
    }

    float acc[4][8][4];
#pragma unroll
    for (int mf = 0; mf < 4; mf++)
#pragma unroll
        for (int nf = 0; nf < 8; nf++)
#pragma unroll
            for (int i = 0; i < 4; i++) acc[mf][nf][i] = 0.f;

#define LOADA(dst, kt) do { \
        if (PACKED_A) { \
            _Pragma("unroll") \
            for (int mf = 0; mf < 4; mf++) { \
                uint4 u = aP[(size_t)mf * aStep + (size_t)(kt) * 32]; \
                dst[mf][0] = u.x; dst[mf][1] = u.y; dst[mf][2] = u.z; dst[mf][3] = u.w; \
            } \
        } else { \
            _Pragma("unroll") \
            for (int mf = 0; mf < 4; mf++) { \
                int ko = (kt) * 8; \
                dst[mf][0] = f2tf32(a0p[mf][ko]); \
                dst[mf][1] = f2tf32(a1p[mf][ko]); \
                dst[mf][2] = f2tf32(a0p[mf][ko + 4]); \
                dst[mf][3] = f2tf32(a1p[mf][ko + 4]); \
            } \
        } \
    } while (0)

#define LOADB(dst, kt) do { \
        _Pragma("unroll") \
        for (int nf = 0; nf < 8; nf++) { \
            uint2 u = bP[(size_t)nf * bStep + (size_t)(kt) * 32]; \
            dst[nf][0] = u.x; dst[nf][1] = u.y; \
        } \
    } while (0)

#define DOMMA(a, b) do { \
        _Pragma("unroll") \
        for (int nf = 0; nf < 8; nf++) \
            _Pragma("unroll") \
            for (int mf = 0; mf < 4; mf++) \
                mma16n8k8(acc[mf][nf], a[mf], b[nf][0], b[nf][1]); \
    } while (0)

    uint32_t aA[4][4], aB[4][4], bA[8][2], bB[8][2];
    LOADA(aA, 0); LOADB(bA, 0);
    for (int kt = 0; kt < KT; kt += 2) {
        LOADA(aB, kt + 1); LOADB(bB, kt + 1);
        DOMMA(aA, bA);
        if (kt + 2 < KT) { LOADA(aA, kt + 2); LOADB(bA, kt + 2); }
        DOMMA(aB, bB);
    }
#undef LOADA
#undef LOADB
#undef DOMMA

#pragma unroll
    for (int mf = 0; mf < 4; mf++) {
        int r = m0 + wm * 64 + mf * 16 + g;
#pragma unroll
        for (int nf = 0; nf < 8; nf++) {
            int col = n0 + wn * 64 + nf * 8 + 2 * tg;
            float2 v0; v0.x = acc[mf][nf][0]; v0.y = acc[mf][nf][1];
            float2 v1; v1.x = acc[mf][nf][2]; v1.y = acc[mf][nf][3];
            *(float2*)(C + (size_t)r * N + col) = v0;
            *(float2*)(C + (size_t)(r + 8) * N + col) = v1;
        }
    }
}

// ---------------- RoPE (in place), layout [b,s,nh,HD] --------------------------
__global__ void rope_kernel(float* __restrict__ x, int nheads, int total)
{
    int idx = blockIdx.x * blockDim.x + threadIdx.x;
    if (idx >= total) return;
    int j = idx & 63;
    int rem = idx >> 6;
    int h = rem % nheads;
    int bs = rem / nheads;
    int s = bs % SS;

    float inv = expf(-(float)j * (logf(10000.0f) / 64.0f));
    float ang = (float)s * inv;
    float c = cosf(ang), sn = sinf(ang);

    float* p = x + ((size_t)bs * nheads + h) * HD;
    float x1 = p[j], x2 = p[j + 64];
    p[j]      = x1 * c - x2 * sn;
    p[j + 64] = x2 * c + x1 * sn;
}

// ---------------- Flash attention (bf16x2 tensor cores, causal GQA) ------------
#define QPITCH 136
#define VPITCH 72
#define OFF_QH 0
#define OFF_QL (OFF_QH + 128*QPITCH)
#define OFF_KH (OFF_QL + 128*QPITCH)
#define OFF_KL (OFF_KH + 64*QPITCH)
#define OFF_VH (OFF_KL + 64*QPITCH)
#define OFF_VL (OFF_VH + 128*VPITCH)
#define OFF_PH (OFF_VL + 128*VPITCH)
#define OFF_PL (OFF_PH + 128*VPITCH)
#define FLASH_SMEM ((OFF_PL + 128*VPITCH) * 2)

__device__ __forceinline__ void split_store(__nv_bfloat16* dh, __nv_bfloat16* dl,
                                            float x0, float x1) {
    __nv_bfloat16 h0 = __float2bfloat16(x0);
    __nv_bfloat16 h1 = __float2bfloat16(x1);
    __nv_bfloat162 hv; hv.x = h0; hv.y = h1;
    __nv_bfloat162 lv;
    lv.x = __float2bfloat16(x0 - __bfloat162float(h0));
    lv.y = __float2bfloat16(x1 - __bfloat162float(h1));
    *(__nv_bfloat162*)dh = hv;
    *(__nv_bfloat162*)dl = lv;
}

__global__ __launch_bounds__(256, 1) void flash_mma(
    const float* __restrict__ Q, const float* __restrict__ K,
    const float* __restrict__ V, float* __restrict__ Aout)
{
    extern __shared__ __nv_bfloat16 fs[];
    __nv_bfloat16* Qh = fs + OFF_QH;
    __nv_bfloat16* Ql = fs + OFF_QL;
    __nv_bfloat16* Kh = fs + OFF_KH;
    __nv_bfloat16* Kl = fs + OFF_KL;
    __nv_bfloat16* Vh = fs + OFF_VH;
    __nv_bfloat16* Vl = fs + OFF_VL;
    __nv_bfloat16* Ph = fs + OFF_PH;
    __nv_bfloat16* Pl = fs + OFF_PL;

    int tid = threadIdx.x, lane = tid & 31, wm = tid >> 5;
    int g = lane >> 2, tg = lane & 3;
    int qt = blockIdx.x, h = blockIdx.y, b = blockIdx.z;
    int kvh = h >> 2;
    int q0 = qt * 128;
    const float scale = 0.08838834764831845f;
    const float NEGINF = __int_as_float(0xff800000);

    {
        int r = tid >> 1, c0 = (tid & 1) * 64;
        const float* src = Q + (((size_t)b * SS + q0 + r) * NH + h) * HD + c0;
        __nv_bfloat16* dh = Qh + r * QPITCH + c0;
        __nv_bfloat16* dl = Ql + r * QPITCH + c0;
#pragma unroll
        for (int i = 0; i < 16; i++) {
            float4 v = ((const float4*)src)[i];
            v.x *= scale; v.y *= scale; v.z *= scale; v.w *= scale;
            split_store(dh + 4 * i,     dl + 4 * i,     v.x, v.y);
            split_store(dh + 4 * i + 2, dl + 4 * i + 2, v.z, v.w);
        }
    }

    float accO[16][4];
#pragma unroll
    for (int nf = 0; nf < 16; nf++)
#pragma unroll
        for (int i = 0; i < 4; i++) accO[nf][i] = 0.f;
    float m0 = NEGINF, m1 = NEGINF, l0 = 0.f, l1 = 0.f;

    int nkt = 2 * (qt + 1);
    for (int kt = 0; kt < nkt; kt++) {
        __syncthreads();
        int k0g = kt * 64;
        {
            int r = tid >> 2, c0 = (tid & 3) * 32;
            const float* src = K + (((size_t)b * SS + k0g + r) * NKV + kvh) * HD + c0;
            __nv_bfloat16* dh = Kh + r * QPITCH + c0;
            __nv_bfloat16* dl = Kl + r * QPITCH + c0;
#pragma unroll
            for (int i = 0; i < 8; i++) {
                float4 v = ((const float4*)src)[i];
                split_store(dh + 4 * i,     dl + 4 * i,     v.x, v.y);
                split_store(dh + 4 * i + 2, dl + 4 * i + 2, v.z, v.w);
            }
        }
#pragma unroll
        for (int u = 0; u < 4; u++) {
            int uu = tid + u * 256;
            int p = uu & 31, cg = uu >> 5;
            const float* s0 = V + (((size_t)b * SS + k0g + 2 * p) * NKV + kvh) * HD + cg * 4;
            float4 v0 = *(const float4*)s0;
            float4 v1 = *(const float4*)(s0 + NKV * HD);
            float a0[4] = {v0.x, v0.y, v0.z, v0.w};
            float a1[4] = {v1.x, v1.y, v1.z, v1.w};
#pragma unroll
            for (int j = 0; j < 4; j++) {
                int d = cg * 4 + j;
                int kp = p ^ (d & 7);
                split_store(Vh + d * VPITCH + 2 * kp, Vl + d * VPITCH + 2 * kp,
                            a0[j], a1[j]);
            }
        }
        __syncthreads();

        bool active = (q0 + wm * 16 + 15) >= k0g;
        if (active) {
            float S[8][4];
#pragma unroll
            for (int nf = 0; nf < 8; nf++)
#pragma unroll
                for (int i = 0; i < 4; i++) S[nf][i] = 0.f;

#pragma unroll
            for (int kc = 0; kc < 8; kc++) {
                uint32_t ah[4], al[4];
                const __nv_bfloat16* qb = Qh + (wm * 16 + g) * QPITCH + kc * 16 + 2 * tg;
                ah[0] = *(const uint32_t*)(qb);
                ah[1] = *(const uint32_t*)(qb + 8 * QPITCH);
                ah[2] = *(const uint32_t*)(qb + 8);
                ah[3] = *(const uint32_t*)(qb + 8 * QPITCH + 8);
                const __nv_bfloat16* ql = Ql + (wm * 16 + g) * QPITCH + kc * 16 + 2 * tg;
                al[0] = *(const uint32_t*)(ql);
                al[1] = *(const uint32_t*)(ql + 8 * QPITCH);
                al[2] = *(const uint32_t*)(ql + 8);
                al[3] = *(const uint32_t*)(ql + 8 * QPITCH + 8);
#pragma unroll
                for (int nf = 0; nf < 8; nf++) {
                    const __nv_bfloat16* kb = Kh + (nf * 8 + g) * QPITCH + kc * 16 + 2 * tg;
                    uint32_t bh0 = *(const uint32_t*)(kb);
                    uint32_t bh1 = *(const uint32_t*)(kb + 8);
                    const __nv_bfloat16* kl = Kl + (nf * 8 + g) * QPITCH + kc * 16 + 2 * tg;
                    uint32_t bl0 = *(const uint32_t*)(kl);
                    uint32_t bl1 = *(const uint32_t*)(kl + 8);
                    mma_bf16(S[nf], ah, bh0, bh1);
                    mma_bf16(S[nf], ah, bl0, bl1);
                    mma_bf16(S[nf], al, bh0, bh1);
                }
            }
            if (k0g + 63 > q0 + wm * 16) {
                int row0 = q0 + wm * 16 + g, row1 = row0 + 8;
#pragma unroll
                for (int nf = 0; nf < 8; nf++) {
                    int col = k0g + nf * 8 + 2 * tg;
                    if (col     > row0) S[nf][0] = NEGINF;
                    if (col + 1 > row0) S[nf][1] = NEGINF;
                    if (col     > row1) S[nf][2] = NEGINF;
                    if (col + 1 > row1) S[nf][3] = NEGINF;
                }
            }
            float mx0 = NEGINF, mx1 = NEGINF;
#pragma unroll
            for (int nf = 0; nf < 8; nf++) {
                mx0 = fmaxf(mx0, fmaxf(S[nf][0], S[nf][1]));
                mx1 = fmaxf(mx1, fmaxf(S[nf][2], S[nf][3]));
            }
            mx0 = fmaxf(mx0, __shfl_xor_sync(0xffffffff, mx0, 1));
            mx0 = fmaxf(mx0, __shfl_xor_sync(0xffffffff, mx0, 2));
            mx1 = fmaxf(mx1, __shfl_xor_sync(0xffffffff, mx1, 1));
            mx1 = fmaxf(mx1, __shfl_xor_sync(0xffffffff, mx1, 2));
            float m0n = fmaxf(m0, mx0), m1n = fmaxf(m1, mx1);
            float al0 = __expf(m0 - m0n), al1 = __expf(m1 - m1n);
            m0 = m0n; m1 = m1n;

            float sum0 = 0.f, sum1 = 0.f;
            int pr0 = (wm * 16 + g) * VPITCH, pr1 = (wm * 16 + g + 8) * VPITCH;
#pragma unroll
            for (int nf = 0; nf < 8; nf++) {
                float p00 = __expf(S[nf][0] - m0);
                float p01 = __expf(S[nf][1] - m0);
                float p10 = __expf(S[nf][2] - m1);
                float p11 = __expf(S[nf][3] - m1);
                sum0 += p00 + p01;
                sum1 += p10 + p11;
                int co = nf * 8 + 2 * tg;
                split_store(Ph + pr0 + co, Pl + pr0 + co, p00, p01);
                split_store(Ph + pr1 + co, Pl + pr1 + co, p10, p11);
            }
            sum0 += __shfl_xor_sync(0xffffffff, sum0, 1);
            sum0 += __shfl_xor_sync(0xffffffff, sum0, 2);
            sum1 += __shfl_xor_sync(0xffffffff, sum1, 1);
            sum1 += __shfl_xor_sync(0xffffffff, sum1, 2);
            l0 = l0 * al0 + sum0;
            l1 = l1 * al1 + sum1;
#pragma unroll
            for (int nf = 0; nf < 16; nf++) {
                accO[nf][0] *= al0; accO[nf][1] *= al0;
                accO[nf][2] *= al1; accO[nf][3] *= al1;
            }
            __syncwarp();
#pragma unroll
            for (int kc = 0; kc < 4; kc++) {
                uint32_t pah[4], pal[4];
                const __nv_bfloat16* pb = Ph + (wm * 16 + g) * VPITCH + kc * 16 + 2 * tg;
                pah[0] = *(const uint32_t*)(pb);
                pah[1] = *(const uint32_t*)(pb + 8 * VPITCH);
                pah[2] = *(const uint32_t*)(pb + 8);
                pah[3] = *(const uint32_t*)(pb + 8 * VPITCH + 8);
                const __nv_bfloat16* pl = Pl + (wm * 16 + g) * VPITCH + kc * 16 + 2 * tg;
                pal[0] = *(const uint32_t*)(pl);
                pal[1] = *(const uint32_t*)(pl + 8 * VPITCH);
                pal[2] = *(const uint32_t*)(pl + 8);
                pal[3] = *(const uint32_t*)(pl + 8 * VPITCH + 8);
#pragma unroll
                for (int nf = 0; nf < 16; nf++) {
                    int n = nf * 8 + g;
                    int i0 = (8 * kc + tg) ^ (n & 7);
                    int i1 = (8 * kc + tg + 4) ^ (n & 7);
                    uint32_t bh0 = *(const uint32_t*)(Vh + n * VPITCH + 2 * i0);
                    uint32_t bh1 = *(const uint32_t*)(Vh + n * VPITCH + 2 * i1);
                    uint32_t bl0 = *(const uint32_t*)(Vl + n * VPITCH + 2 * i0);
                    uint32_t bl1 = *(const uint32_t*)(Vl + n * VPITCH + 2 * i1);
                    mma_bf16(accO[nf], pah, bh0, bh1);
                    mma_bf16(accO[nf], pah, bl0, bl1);
                    mma_bf16(accO[nf], pal, bh0, bh1);
                }
            }
        }
    }

    float i0 = 1.0f / l0, i1 = 1.0f / l1;
    int r0 = q0 + wm * 16 + g;
    float* o0 = Aout + (((size_t)b * SS + r0) * NH + h) * HD;
    float* o1 = o0 + (size_t)8 * NH * HD;
#pragma unroll
    for (int nf = 0; nf < 16; nf++) {
        int d = nf * 8 + 2 * tg;
        float2 v0; v0.x = accO[nf][0] * i0; v0.y = accO[nf][1] * i0;
        float2 v1; v1.x = accO[nf][2] * i1; v1.y = accO[nf][3] * i1;
        *(float2*)(o0 + d) = v0;
        *(float2*)(o1 + d) = v1;
    }
}

// ---------------- launch --------------------------------------------------------
extern "C" void kernel_launch(void* const* d_in, const int* in_sizes, int n_in,
                              void* d_out, int out_size)
{
    const float* x  = (const float*)d_in[0];
    const float* wq = (const float*)d_in[1];
    const float* wk = (const float*)d_in[2];
    const float* wv = (const float*)d_in[3];
    const float* wo = (const float*)d_in[4];
    float* out = (float*)d_out;

    float *Qp, *Kp, *Vp, *Ap;
    uint32_t *Xp, *Wqp, *Wkp, *Wvp, *Wop;
    cudaGetSymbolAddress((void**)&Qp, g_Q);
    cudaGetSymbolAddress((void**)&Kp, g_K);
    cudaGetSymbolAddress((void**)&Vp, g_V);
    cudaGetSymbolAddress((void**)&Ap, g_A);
    cudaGetSymbolAddress((void**)&Xp, g_Xp);
    cudaGetSymbolAddress((void**)&Wqp, g_Wqp);
    cudaGetSymbolAddress((void**)&Wkp, g_Wkp);
    cudaGetSymbolAddress((void**)&Wvp, g_Wvp);
    cudaGetSymbolAddress((void**)&Wop, g_Wop);

    cudaFuncSetAttribute(flash_mma, cudaFuncAttributeMaxDynamicSharedMemorySize, FLASH_SMEM);

    // pack weights + x (tf32 bits, fragment-major)
    pack_a<<<(MROWS/16)*(HIDDEN/8)*32/256, 256>>>(x, Xp, MROWS, HIDDEN);
    pack_b<<<((NH*HD)/8)*(HIDDEN/8)*32/256, 256>>>(wq, Wqp, NH*HD, HIDDEN);
    pack_b<<<((NKV*HD)/8)*(HIDDEN/8)*32/256, 256>>>(wk, Wkp, NKV*HD, HIDDEN);
    pack_b<<<((NKV*HD)/8)*(HIDDEN/8)*32/256, 256>>>(wv, Wvp, NKV*HD, HIDDEN);
    pack_b<<<(HIDDEN/8)*((NH*HD)/8)*32/256, 256>>>(wo, Wop, HIDDEN, NH*HD);

    // Projections (fragment-direct TF32 mma)
    gemm_fp<1><<<dim3((NH*HD)/256, MROWS/128), 256>>>(nullptr, Xp, Wqp, Qp, MROWS, NH*HD, HIDDEN);
    gemm_fp<1><<<dim3((NKV*HD)/256, MROWS/128), 256>>>(nullptr, Xp, Wkp, Kp, MROWS, NKV*HD, HIDDEN);
    gemm_fp<1><<<dim3((NKV*HD)/256, MROWS/128), 256>>>(nullptr, Xp, Wvp, Vp, MROWS, NKV*HD, HIDDEN);

    // RoPE
    int nq = MROWS * NH * 64;
    rope_kernel<<<(nq + 255) / 256, 256>>>(Qp, NH, nq);
    int nk = MROWS * NKV * 64;
    rope_kernel<<<(nk + 255) / 256, 256>>>(Kp, NKV, nk);

    // Flash attention (bf16x2 tensor cores)
    flash_mma<<<dim3(SS / 128, NH, BB), 256, FLASH_SMEM>>>(Qp, Kp, Vp, Ap);

    // Output projection (A raw float, B packed)
    gemm_fp<0><<<dim3(HIDDEN/256, MROWS/128), 256>>>(Ap, nullptr, Wop, out, MROWS, HIDDEN, NH*HD);
}

// round 8
// speedup vs baseline: 3.7394x; 1.3278x over previous
#include <cuda_runtime.h>
#include <cuda_bf16.h>
#include <math.h>
#include <stdint.h>

#define HIDDEN 4096
#define NH 32
#define NKV 8
#define HD 128
#define BB 2
#define SS 2048
#define MROWS (BB*SS)   /* 4096 */

// ---------------- scratch -----------------------------------------------------
__device__ float g_Q[(size_t)MROWS * NH * HD];
__device__ float g_K[(size_t)MROWS * NKV * HD];
__device__ float g_V[(size_t)MROWS * NKV * HD];
__device__ float g_A[(size_t)MROWS * NH * HD];
// packed (tf32 bits, mma-fragment-major)
__device__ uint32_t g_Xp [(size_t)MROWS * HIDDEN];
__device__ uint32_t g_Ap [(size_t)MROWS * NH * HD];
__device__ uint32_t g_Wqp[(size_t)NH  * HD * HIDDEN];
__device__ uint32_t g_Wkp[(size_t)NKV * HD * HIDDEN];
__device__ uint32_t g_Wvp[(size_t)NKV * HD * HIDDEN];
__device__ uint32_t g_Wop[(size_t)HIDDEN * NH * HD];

__device__ __forceinline__ uint32_t f2tf32(float f) {
    uint32_t r; asm("cvt.rna.tf32.f32 %0, %1;" : "=r"(r) : "f"(f)); return r;
}

__device__ __forceinline__ void mma16n8k8(float* d, const uint32_t* a,
                                          uint32_t b0, uint32_t b1) {
    asm volatile(
        "mma.sync.aligned.m16n8k8.row.col.f32.tf32.tf32.f32 "
        "{%0,%1,%2,%3}, {%4,%5,%6,%7}, {%8,%9}, {%0,%1,%2,%3};"
        : "+f"(d[0]), "+f"(d[1]), "+f"(d[2]), "+f"(d[3])
        : "r"(a[0]), "r"(a[1]), "r"(a[2]), "r"(a[3]), "r"(b0), "r"(b1));
}

__device__ __forceinline__ void mma_bf16(float* d, const uint32_t* a,
                                         uint32_t b0, uint32_t b1) {
    asm volatile(
        "mma.sync.aligned.m16n8k16.row.col.f32.bf16.bf16.f32 "
        "{%0,%1,%2,%3}, {%4,%5,%6,%7}, {%8,%9}, {%0,%1,%2,%3};"
        : "+f"(d[0]), "+f"(d[1]), "+f"(d[2]), "+f"(d[3])
        : "r"(a[0]), "r"(a[1]), "r"(a[2]), "r"(a[3]), "r"(b0), "r"(b1));
}

// ---------------- packing kernels ---------------------------------------------
__global__ __launch_bounds__(256) void pack_a(const float* __restrict__ X,
                                              uint32_t* __restrict__ Xp,
                                              int M, int K)
{
    int idx = blockIdx.x * 256 + threadIdx.x;
    int total = (M >> 4) * (K >> 3) * 32;
    if (idx >= total) return;
    int lane = idx & 31, t = idx >> 5;
    int KT = K >> 3;
    int kt = t % KT, mt = t / KT;
    int g = lane >> 2, tg = lane & 3;
    size_t r0 = (size_t)(mt * 16 + g) * K + kt * 8 + tg;
    uint4 v;
    v.x = f2tf32(X[r0]);
    v.y = f2tf32(X[r0 + (size_t)8 * K]);
    v.z = f2tf32(X[r0 + 4]);
    v.w = f2tf32(X[r0 + (size_t)8 * K + 4]);
    ((uint4*)Xp)[(size_t)t * 32 + lane] = v;
}

__global__ __launch_bounds__(256) void pack_b(const float* __restrict__ W,
                                              uint32_t* __restrict__ Wp,
                                              int N, int K)
{
    int idx = blockIdx.x * 256 + threadIdx.x;
    int total = (N >> 3) * (K >> 3) * 32;
    if (idx >= total) return;
    int lane = idx & 31, t = idx >> 5;
    int KT = K >> 3;
    int kt = t % KT, nt = t / KT;
    int g = lane >> 2, tg = lane & 3;
    size_t r0 = (size_t)(nt * 8 + g) * K + kt * 8 + tg;
    uint2 v;
    v.x = f2tf32(W[r0]);
    v.y = f2tf32(W[r0 + 4]);
    ((uint2*)Wp)[(size_t)t * 32 + lane] = v;
}

// ---------------- fragment-direct TF32 GEMM: C = A * W^T -----------------------
// 128x128 tile, 8 warps (2x4: warp tile 64x32), 2 CTAs/SM, no smem.
__global__ __launch_bounds__(256, 2) void gemm_fp(
    const uint32_t* __restrict__ Apk, const uint32_t* __restrict__ Bp,
    float* __restrict__ C, int M, int N, int K)
{
    int tid = threadIdx.x;
    int lane = tid & 31, wid = tid >> 5;
    int wm = wid & 1, wn = wid >> 1;
    int g = lane >> 2, tg = lane & 3;
    int m0 = blockIdx.y * 128;
    int n0 = blockIdx.x * 128;
    const int KT = K >> 3;

    const uint4* aP = (const uint4*)Apk + ((size_t)((m0 >> 4) + wm * 4) * KT) * 32 + lane;
    const uint2* bP = (const uint2*)Bp + ((size_t)((n0 >> 3) + wn * 4) * KT) * 32 + lane;
    const size_t aStep = (size_t)KT * 32;   // per mtile (uint4)
    const size_t bStep = (size_t)KT * 32;   // per ntile (uint2)

    float acc[4][4][4];
#pragma unroll
    for (int mf = 0; mf < 4; mf++)
#pragma unroll
        for (int nf = 0; nf < 4; nf++)
#pragma unroll
            for (int i = 0; i < 4; i++) acc[mf][nf][i] = 0.f;

#define LOADA(dst, kt) do { \
        _Pragma("unroll") \
        for (int mf = 0; mf < 4; mf++) { \
            uint4 u = aP[(size_t)mf * aStep + (size_t)(kt) * 32]; \
            dst[mf][0] = u.x; dst[mf][1] = u.y; dst[mf][2] = u.z; dst[mf][3] = u.w; \
        } \
    } while (0)

#define LOADB(dst, kt) do { \
        _Pragma("unroll") \
        for (int nf = 0; nf < 4; nf++) { \
            uint2 u = bP[(size_t)nf * bStep + (size_t)(kt) * 32]; \
            dst[nf][0] = u.x; dst[nf][1] = u.y; \
        } \
    } while (0)

#define DOMMA(a, b) do { \
        _Pragma("unroll") \
        for (int nf = 0; nf < 4; nf++) \
            _Pragma("unroll") \
            for (int mf = 0; mf < 4; mf++) \
                mma16n8k8(acc[mf][nf], a[mf], b[nf][0], b[nf][1]); \
    } while (0)

    uint32_t aA[4][4], aB[4][4], bA[4][2], bB[4][2];
    LOADA(aA, 0); LOADB(bA, 0);
    for (int kt = 0; kt < KT; kt += 2) {
        LOADA(aB, kt + 1); LOADB(bB, kt + 1);
        DOMMA(aA, bA);
        if (kt + 2 < KT) { LOADA(aA, kt + 2); LOADB(bA, kt + 2); }
        DOMMA(aB, bB);
    }
#undef LOADA
#undef LOADB
#undef DOMMA

#pragma unroll
    for (int mf = 0; mf < 4; mf++) {
        int r = m0 + wm * 64 + mf * 16 + g;
#pragma unroll
        for (int nf = 0; nf < 4; nf++) {
            int col = n0 + wn * 32 + nf * 8 + 2 * tg;
            float2 v0; v0.x = acc[mf][nf][0]; v0.y = acc[mf][nf][1];
            float2 v1; v1.x = acc[mf][nf][2]; v1.y = acc[mf][nf][3];
            *(float2*)(C + (size_t)r * N + col) = v0;
            *(float2*)(C + (size_t)(r + 8) * N + col) = v1;
        }
    }
}

// ---------------- RoPE (in place), layout [b,s,nh,HD] --------------------------
__global__ void rope_kernel(float* __restrict__ x, int nheads, int total)
{
    int idx = blockIdx.x * blockDim.x + threadIdx.x;
    if (idx >= total) return;
    int j = idx & 63;
    int rem = idx >> 6;
    int h = rem % nheads;
    int bs = rem / nheads;
    int s = bs % SS;

    float inv = expf(-(float)j * (logf(10000.0f) / 64.0f));
    float ang = (float)s * inv;
    float c = cosf(ang), sn = sinf(ang);

    float* p = x + ((size_t)bs * nheads + h) * HD;
    float x1 = p[j], x2 = p[j + 64];
    p[j]      = x1 * c - x2 * sn;
    p[j + 64] = x2 * c + x1 * sn;
}

// ---------------- Flash attention (bf16x2 tensor cores, causal GQA) ------------
#define QPITCH 136
#define VPITCH 72
#define OFF_QH 0
#define OFF_QL (OFF_QH + 128*QPITCH)
#define OFF_KH (OFF_QL + 128*QPITCH)
#define OFF_KL (OFF_KH + 64*QPITCH)
#define OFF_VH (OFF_KL + 64*QPITCH)
#define OFF_VL (OFF_VH + 128*VPITCH)
#define OFF_PH (OFF_VL + 128*VPITCH)
#define OFF_PL (OFF_PH + 128*VPITCH)
#define FLASH_SMEM ((OFF_PL + 128*VPITCH) * 2)

__device__ __forceinline__ void split_store(__nv_bfloat16* dh, __nv_bfloat16* dl,
                                            float x0, float x1) {
    __nv_bfloat16 h0 = __float2bfloat16(x0);
    __nv_bfloat16 h1 = __float2bfloat16(x1);
    __nv_bfloat162 hv; hv.x = h0; hv.y = h1;
    __nv_bfloat162 lv;
    lv.x = __float2bfloat16(x0 - __bfloat162float(h0));
    lv.y = __float2bfloat16(x1 - __bfloat162float(h1));
    *(__nv_bfloat162*)dh = hv;
    *(__nv_bfloat162*)dl = lv;
}

__global__ __launch_bounds__(256, 1) void flash_mma(
    const float* __restrict__ Q, const float* __restrict__ K,
    const float* __restrict__ V, float* __restrict__ Aout)
{
    extern __shared__ __nv_bfloat16 fs[];
    __nv_bfloat16* Qh = fs + OFF_QH;
    __nv_bfloat16* Ql = fs + OFF_QL;
    __nv_bfloat16* Kh = fs + OFF_KH;
    __nv_bfloat16* Kl = fs + OFF_KL;
    __nv_bfloat16* Vh = fs + OFF_VH;
    __nv_bfloat16* Vl = fs + OFF_VL;
    __nv_bfloat16* Ph = fs + OFF_PH;
    __nv_bfloat16* Pl = fs + OFF_PL;

    int tid = threadIdx.x, lane = tid & 31, wm = tid >> 5;
    int g = lane >> 2, tg = lane & 3;
    int qt = blockIdx.x, h = blockIdx.y, b = blockIdx.z;
    int kvh = h >> 2;
    int q0 = qt * 128;
    const float scale = 0.08838834764831845f;
    const float NEGINF = __int_as_float(0xff800000);

    {
        int r = tid >> 1, c0 = (tid & 1) * 64;
        const float* src = Q + (((size_t)b * SS + q0 + r) * NH + h) * HD + c0;
        __nv_bfloat16* dh = Qh + r * QPITCH + c0;
        __nv_bfloat16* dl = Ql + r * QPITCH + c0;
#pragma unroll
        for (int i = 0; i < 16; i++) {
            float4 v = ((const float4*)src)[i];
            v.x *= scale; v.y *= scale; v.z *= scale; v.w *= scale;
            split_store(dh + 4 * i,     dl + 4 * i,     v.x, v.y);
            split_store(dh + 4 * i + 2, dl + 4 * i + 2, v.z, v.w);
        }
    }

    float accO[16][4];
#pragma unroll
    for (int nf = 0; nf < 16; nf++)
#pragma unroll
        for (int i = 0; i < 4; i++) accO[nf][i] = 0.f;
    float m0 = NEGINF, m1 = NEGINF, l0 = 0.f, l1 = 0.f;

    int nkt = 2 * (qt + 1);
    for (int kt = 0; kt < nkt; kt++) {
        __syncthreads();
        int k0g = kt * 64;
        {
            int r = tid >> 2, c0 = (tid & 3) * 32;
            const float* src = K + (((size_t)b * SS + k0g + r) * NKV + kvh) * HD + c0;
            __nv_bfloat16* dh = Kh + r * QPITCH + c0;
            __nv_bfloat16* dl = Kl + r * QPITCH + c0;
#pragma unroll
            for (int i = 0; i < 8; i++) {
                float4 v = ((const float4*)src)[i];
                split_store(dh + 4 * i,     dl + 4 * i,     v.x, v.y);
                split_store(dh + 4 * i + 2, dl + 4 * i + 2, v.z, v.w);
            }
        }
#pragma unroll
        for (int u = 0; u < 4; u++) {
            int uu = tid + u * 256;
            int p = uu & 31, cg = uu >> 5;
            const float* s0 = V + (((size_t)b * SS + k0g + 2 * p) * NKV + kvh) * HD + cg * 4;
            float4 v0 = *(const float4*)s0;
            float4 v1 = *(const float4*)(s0 + NKV * HD);
            float a0[4] = {v0.x, v0.y, v0.z, v0.w};
            float a1[4] = {v1.x, v1.y, v1.z, v1.w};
#pragma unroll
            for (int j = 0; j < 4; j++) {
                int d = cg * 4 + j;
                int kp = p ^ (d & 7);
                split_store(Vh + d * VPITCH + 2 * kp, Vl + d * VPITCH + 2 * kp,
                            a0[j], a1[j]);
            }
        }
        __syncthreads();

        bool active = (q0 + wm * 16 + 15) >= k0g;
        if (active) {
            float S[8][4];
#pragma unroll
            for (int nf = 0; nf < 8; nf++)
#pragma unroll
                for (int i = 0; i < 4; i++) S[nf][i] = 0.f;

#pragma unroll
            for (int kc = 0; kc < 8; kc++) {
                uint32_t ah[4], al[4];
                const __nv_bfloat16* qb = Qh + (wm * 16 + g) * QPITCH + kc * 16 + 2 * tg;
                ah[0] = *(const uint32_t*)(qb);
                ah[1] = *(const uint32_t*)(qb + 8 * QPITCH);
                ah[2] = *(const uint32_t*)(qb + 8);
                ah[3] = *(const uint32_t*)(qb + 8 * QPITCH + 8);
                const __nv_bfloat16* ql = Ql + (wm * 16 + g) * QPITCH + kc * 16 + 2 * tg;
                al[0] = *(const uint32_t*)(ql);
                al[1] = *(const uint32_t*)(ql + 8 * QPITCH);
                al[2] = *(const uint32_t*)(ql + 8);
                al[3] = *(const uint32_t*)(ql + 8 * QPITCH + 8);
#pragma unroll
                for (int nf = 0; nf < 8; nf++) {
                    const __nv_bfloat16* kb = Kh + (nf * 8 + g) * QPITCH + kc * 16 + 2 * tg;
                    uint32_t bh0 = *(const uint32_t*)(kb);
                    uint32_t bh1 = *(const uint32_t*)(kb + 8);
                    const __nv_bfloat16* kl = Kl + (nf * 8 + g) * QPITCH + kc * 16 + 2 * tg;
                    uint32_t bl0 = *(const uint32_t*)(kl);
                    uint32_t bl1 = *(const uint32_t*)(kl + 8);
                    mma_bf16(S[nf], ah, bh0, bh1);
                    mma_bf16(S[nf], ah, bl0, bl1);
                    mma_bf16(S[nf], al, bh0, bh1);
                }
            }
            if (k0g + 63 > q0 + wm * 16) {
                int row0 = q0 + wm * 16 + g, row1 = row0 + 8;
#pragma unroll
                for (int nf = 0; nf < 8; nf++) {
                    int col = k0g + nf * 8 + 2 * tg;
                    if (col     > row0) S[nf][0] = NEGINF;
                    if (col + 1 > row0) S[nf][1] = NEGINF;
                    if (col     > row1) S[nf][2] = NEGINF;
                    if (col + 1 > row1) S[nf][3] = NEGINF;
                }
            }
            float mx0 = NEGINF, mx1 = NEGINF;
#pragma unroll
            for (int nf = 0; nf < 8; nf++) {
                mx0 = fmaxf(mx0, fmaxf(S[nf][0], S[nf][1]));
                mx1 = fmaxf(mx1, fmaxf(S[nf][2], S[nf][3]));
            }
            mx0 = fmaxf(mx0, __shfl_xor_sync(0xffffffff, mx0, 1));
            mx0 = fmaxf(mx0, __shfl_xor_sync(0xffffffff, mx0, 2));
            mx1 = fmaxf(mx1, __shfl_xor_sync(0xffffffff, mx1, 1));
            mx1 = fmaxf(mx1, __shfl_xor_sync(0xffffffff, mx1, 2));
            float m0n = fmaxf(m0, mx0), m1n = fmaxf(m1, mx1);
            float al0 = __expf(m0 - m0n), al1 = __expf(m1 - m1n);
            m0 = m0n; m1 = m1n;

            float sum0 = 0.f, sum1 = 0.f;
            int pr0 = (wm * 16 + g) * VPITCH, pr1 = (wm * 16 + g + 8) * VPITCH;
#pragma unroll
            for (int nf = 0; nf < 8; nf++) {
                float p00 = __expf(S[nf][0] - m0);
                float p01 = __expf(S[nf][1] - m0);
                float p10 = __expf(S[nf][2] - m1);
                float p11 = __expf(S[nf][3] - m1);
                sum0 += p00 + p01;
                sum1 += p10 + p11;
                int co = nf * 8 + 2 * tg;
                split_store(Ph + pr0 + co, Pl + pr0 + co, p00, p01);
                split_store(Ph + pr1 + co, Pl + pr1 + co, p10, p11);
            }
            sum0 += __shfl_xor_sync(0xffffffff, sum0, 1);
            sum0 += __shfl_xor_sync(0xffffffff, sum0, 2);
            sum1 += __shfl_xor_sync(0xffffffff, sum1, 1);
            sum1 += __shfl_xor_sync(0xffffffff, sum1, 2);
            l0 = l0 * al0 + sum0;
            l1 = l1 * al1 + sum1;
#pragma unroll
            for (int nf = 0; nf < 16; nf++) {
                accO[nf][0] *= al0; accO[nf][1] *= al0;
                accO[nf][2] *= al1; accO[nf][3] *= al1;
            }
            __syncwarp();
#pragma unroll
            for (int kc = 0; kc < 4; kc++) {
                uint32_t pah[4], pal[4];
                const __nv_bfloat16* pb = Ph + (wm * 16 + g) * VPITCH + kc * 16 + 2 * tg;
                pah[0] = *(const uint32_t*)(pb);
                pah[1] = *(const uint32_t*)(pb + 8 * VPITCH);
                pah[2] = *(const uint32_t*)(pb + 8);
                pah[3] = *(const uint32_t*)(pb + 8 * VPITCH + 8);
                const __nv_bfloat16* pl = Pl + (wm * 16 + g) * VPITCH + kc * 16 + 2 * tg;
                pal[0] = *(const uint32_t*)(pl);
                pal[1] = *(const uint32_t*)(pl + 8 * VPITCH);
                pal[2] = *(const uint32_t*)(pl + 8);
                pal[3] = *(const uint32_t*)(pl + 8 * VPITCH + 8);
#pragma unroll
                for (int nf = 0; nf < 16; nf++) {
                    int n = nf * 8 + g;
                    int i0 = (8 * kc + tg) ^ (n & 7);
                    int i1 = (8 * kc + tg + 4) ^ (n & 7);
                    uint32_t bh0 = *(const uint32_t*)(Vh + n * VPITCH + 2 * i0);
                    uint32_t bh1 = *(const uint32_t*)(Vh + n * VPITCH + 2 * i1);
                    uint32_t bl0 = *(const uint32_t*)(Vl + n * VPITCH + 2 * i0);
                    uint32_t bl1 = *(const uint32_t*)(Vl + n * VPITCH + 2 * i1);
                    mma_bf16(accO[nf], pah, bh0, bh1);
                    mma_bf16(accO[nf], pah, bl0, bl1);
                    mma_bf16(accO[nf], pal, bh0, bh1);
                }
            }
        }
    }

    float i0 = 1.0f / l0, i1 = 1.0f / l1;
    int r0 = q0 + wm * 16 + g;
    float* o0 = Aout + (((size_t)b * SS + r0) * NH + h) * HD;
    float* o1 = o0 + (size_t)8 * NH * HD;
#pragma unroll
    for (int nf = 0; nf < 16; nf++) {
        int d = nf * 8 + 2 * tg;
        float2 v0; v0.x = accO[nf][0] * i0; v0.y = accO[nf][1] * i0;
        float2 v1; v1.x = accO[nf][2] * i1; v1.y = accO[nf][3] * i1;
        *(float2*)(o0 + d) = v0;
        *(float2*)(o1 + d) = v1;
    }
}

// ---------------- launch --------------------------------------------------------
extern "C" void kernel_launch(void* const* d_in, const int* in_sizes, int n_in,
                              void* d_out, int out_size)
{
    const float* x  = (const float*)d_in[0];
    const float* wq = (const float*)d_in[1];
    const float* wk = (const float*)d_in[2];
    const float* wv = (const float*)d_in[3];
    const float* wo = (const float*)d_in[4];
    float* out = (float*)d_out;

    float *Qp, *Kp, *Vp, *Ap;
    uint32_t *Xp, *Apk, *Wqp, *Wkp, *Wvp, *Wop;
    cudaGetSymbolAddress((void**)&Qp, g_Q);
    cudaGetSymbolAddress((void**)&Kp, g_K);
    cudaGetSymbolAddress((void**)&Vp, g_V);
    cudaGetSymbolAddress((void**)&Ap, g_A);
    cudaGetSymbolAddress((void**)&Xp, g_Xp);
    cudaGetSymbolAddress((void**)&Apk, g_Ap);
    cudaGetSymbolAddress((void**)&Wqp, g_Wqp);
    cudaGetSymbolAddress((void**)&Wkp, g_Wkp);
    cudaGetSymbolAddress((void**)&Wvp, g_Wvp);
    cudaGetSymbolAddress((void**)&Wop, g_Wop);

    cudaFuncSetAttribute(flash_mma, cudaFuncAttributeMaxDynamicSharedMemorySize, FLASH_SMEM);

    // pack weights + x (tf32 bits, fragment-major)
    pack_a<<<(MROWS/16)*(HIDDEN/8)*32/256, 256>>>(x, Xp, MROWS, HIDDEN);
    pack_b<<<((NH*HD)/8)*(HIDDEN/8)*32/256, 256>>>(wq, Wqp, NH*HD, HIDDEN);
    pack_b<<<((NKV*HD)/8)*(HIDDEN/8)*32/256, 256>>>(wk, Wkp, NKV*HD, HIDDEN);
    pack_b<<<((NKV*HD)/8)*(HIDDEN/8)*32/256, 256>>>(wv, Wvp, NKV*HD, HIDDEN);
    pack_b<<<(HIDDEN/8)*((NH*HD)/8)*32/256, 256>>>(wo, Wop, HIDDEN, NH*HD);

    // Projections (fragment-direct TF32 mma, 128x128 tiles, 2 CTAs/SM)
    gemm_fp<<<dim3((NH*HD)/128, MROWS/128), 256>>>(Xp, Wqp, Qp, MROWS, NH*HD, HIDDEN);
    gemm_fp<<<dim3((NKV*HD)/128, MROWS/128), 256>>>(Xp, Wkp, Kp, MROWS, NKV*HD, HIDDEN);
    gemm_fp<<<dim3((NKV*HD)/128, MROWS/128), 256>>>(Xp, Wvp, Vp, MROWS, NKV*HD, HIDDEN);

    // RoPE
    int nq = MROWS * NH * 64;
    rope_kernel<<<(nq + 255) / 256, 256>>>(Qp, NH, nq);
    int nk = MROWS * NKV * 64;
    rope_kernel<<<(nk + 255) / 256, 256>>>(Kp, NKV, nk);

    // Flash attention (bf16x2 tensor cores)
    flash_mma<<<dim3(SS / 128, NH, BB), 256, FLASH_SMEM>>>(Qp, Kp, Vp, Ap);

    // pack attention output, then output projection
    pack_a<<<(MROWS/16)*((NH*HD)/8)*32/256, 256>>>(Ap, Apk, MROWS, NH*HD);
    gemm_fp<<<dim3(HIDDEN/128, MROWS/128), 256>>>(Apk, Wop, out, MROWS, HIDDEN, NH*HD);
}

// round 9
// speedup vs baseline: 4.2291x; 1.1309x over previous
#include <cuda_runtime.h>
#include <cuda_bf16.h>
#include <math.h>
#include <stdint.h>

#define HIDDEN 4096
#define NH 32
#define NKV 8
#define HD 128
#define BB 2
#define SS 2048
#define MROWS (BB*SS)   /* 4096 */
#define NQKV 6144       /* 4096 + 1024 + 1024 */

// ---------------- scratch -----------------------------------------------------
__device__ float g_QKV[(size_t)MROWS * NQKV];          // [bs][q 4096 | k 1024 | v 1024]
__device__ float g_A[(size_t)MROWS * NH * HD];         // attention out [bs][h*128+d]
__device__ uint32_t g_Xp   [(size_t)MROWS * HIDDEN];   // x packed (tf32 A-frags)
__device__ uint32_t g_Apk  [(size_t)MROWS * NH * HD];  // attn out packed
__device__ uint32_t g_Wqkvp[(size_t)NQKV * HIDDEN];    // fused W packed (tf32 B-frags)
__device__ uint32_t g_Wop  [(size_t)HIDDEN * NH * HD];
__device__ uint4 g_Qpk[(size_t)BB * NH * 128 * 8 * 64];        // Q bf16 hi/lo A-frags (64MB)
__device__ uint4 g_Kpk[(size_t)BB * NKV * 256 * 8 * 32];       // K bf16 hi/lo B-frags (16MB)
__device__ uint4 g_Vtp[(size_t)BB * NKV * 32 * 16 * 4 * 32];   // V^T bf16 hi/lo B-frags (16MB)

__device__ __forceinline__ uint32_t f2tf32(float f) {
    uint32_t r; asm("cvt.rna.tf32.f32 %0, %1;" : "=r"(r) : "f"(f)); return r;
}
__device__ __forceinline__ uint32_t bfpair(float x0, float x1) {
    __nv_bfloat162 h; h.x = __float2bfloat16(x0); h.y = __float2bfloat16(x1);
    return *(uint32_t*)&h;
}
__device__ __forceinline__ uint32_t bfpair_lo(float x0, float x1, uint32_t hi) {
    __nv_bfloat162 h = *(__nv_bfloat162*)&hi;
    return bfpair(x0 - __bfloat162float(h.x), x1 - __bfloat162float(h.y));
}

__device__ __forceinline__ void mma16n8k8(float* d, const uint32_t* a,
                                          uint32_t b0, uint32_t b1) {
    asm volatile(
        "mma.sync.aligned.m16n8k8.row.col.f32.tf32.tf32.f32 "
        "{%0,%1,%2,%3}, {%4,%5,%6,%7}, {%8,%9}, {%0,%1,%2,%3};"
        : "+f"(d[0]), "+f"(d[1]), "+f"(d[2]), "+f"(d[3])
        : "r"(a[0]), "r"(a[1]), "r"(a[2]), "r"(a[3]), "r"(b0), "r"(b1));
}
__device__ __forceinline__ void mma_bf16(float* d, const uint32_t* a,
                                         uint32_t b0, uint32_t b1) {
    asm volatile(
        "mma.sync.aligned.m16n8k16.row.col.f32.bf16.bf16.f32 "
        "{%0,%1,%2,%3}, {%4,%5,%6,%7}, {%8,%9}, {%0,%1,%2,%3};"
        : "+f"(d[0]), "+f"(d[1]), "+f"(d[2]), "+f"(d[3])
        : "r"(a[0]), "r"(a[1]), "r"(a[2]), "r"(a[3]), "r"(b0), "r"(b1));
}

// ---------------- tf32 packing (GEMM operands) ---------------------------------
__global__ __launch_bounds__(256) void pack_a(const float* __restrict__ X,
                                              uint32_t* __restrict__ Xp,
                                              int M, int K)
{
    int idx = blockIdx.x * 256 + threadIdx.x;
    int total = (M >> 4) * (K >> 3) * 32;
    if (idx >= total) return;
    int lane = idx & 31, t = idx >> 5;
    int KT = K >> 3;
    int kt = t % KT, mt = t / KT;
    int g = lane >> 2, tg = lane & 3;
    size_t r0 = (size_t)(mt * 16 + g) * K + kt * 8 + tg;
    uint4 v;
    v.x = f2tf32(X[r0]);
    v.y = f2tf32(X[r0 + (size_t)8 * K]);
    v.z = f2tf32(X[r0 + 4]);
    v.w = f2tf32(X[r0 + (size_t)8 * K + 4]);
    ((uint4*)Xp)[(size_t)t * 32 + lane] = v;
}

__global__ __launch_bounds__(256) void pack_b(const float* __restrict__ W,
                                              uint32_t* __restrict__ Wp,
                                              int N, int K)
{
    int idx = blockIdx.x * 256 + threadIdx.x;
    int total = (N >> 3) * (K >> 3) * 32;
    if (idx >= total) return;
    int lane = idx & 31, t = idx >> 5;
    int KT = K >> 3;
    int kt = t % KT, nt = t / KT;
    int g = lane >> 2, tg = lane & 3;
    size_t r0 = (size_t)(nt * 8 + g) * K + kt * 8 + tg;
    uint2 v;
    v.x = f2tf32(W[r0]);
    v.y = f2tf32(W[r0 + 4]);
    ((uint2*)Wp)[(size_t)t * 32 + lane] = v;
}

// ---------------- fragment-direct TF32 GEMM: C = A * W^T -----------------------
__global__ __launch_bounds__(256, 2) void gemm_fp(
    const uint32_t* __restrict__ Apk, const uint32_t* __restrict__ Bp,
    float* __restrict__ C, int M, int N, int K)
{
    int tid = threadIdx.x;
    int lane = tid & 31, wid = tid >> 5;
    int wm = wid & 1, wn = wid >> 1;
    int g = lane >> 2, tg = lane & 3;
    int m0 = blockIdx.y * 128;
    int n0 = blockIdx.x * 128;
    const int KT = K >> 3;

    const uint4* aP = (const uint4*)Apk + ((size_t)((m0 >> 4) + wm * 4) * KT) * 32 + lane;
    const uint2* bP = (const uint2*)Bp + ((size_t)((n0 >> 3) + wn * 4) * KT) * 32 + lane;
    const size_t aStep = (size_t)KT * 32;
    const size_t bStep = (size_t)KT * 32;

    float acc[4][4][4];
#pragma unroll
    for (int mf = 0; mf < 4; mf++)
#pragma unroll
        for (int nf = 0; nf < 4; nf++)
#pragma unroll
            for (int i = 0; i < 4; i++) acc[mf][nf][i] = 0.f;

#define LOADA(dst, kt) do { \
        _Pragma("unroll") \
        for (int mf = 0; mf < 4; mf++) { \
            uint4 u = aP[(size_t)mf * aStep + (size_t)(kt) * 32]; \
            dst[mf][0] = u.x; dst[mf][1] = u.y; dst[mf][2] = u.z; dst[mf][3] = u.w; \
        } \
    } while (0)
#define LOADB(dst, kt) do { \
        _Pragma("unroll") \
        for (int nf = 0; nf < 4; nf++) { \
            uint2 u = bP[(size_t)nf * bStep + (size_t)(kt) * 32]; \
            dst[nf][0] = u.x; dst[nf][1] = u.y; \
        } \
    } while (0)
#define DOMMA(a, b) do { \
        _Pragma("unroll") \
        for (int nf = 0; nf < 4; nf++) \
            _Pragma("unroll") \
            for (int mf = 0; mf < 4; mf++) \
                mma16n8k8(acc[mf][nf], a[mf], b[nf][0], b[nf][1]); \
    } while (0)

    uint32_t aA[4][4], aB[4][4], bA[4][2], bB[4][2];
    LOADA(aA, 0); LOADB(bA, 0);
    for (int kt = 0; kt < KT; kt += 2) {
        LOADA(aB, kt + 1); LOADB(bB, kt + 1);
        DOMMA(aA, bA);
        if (kt + 2 < KT) { LOADA(aA, kt + 2); LOADB(bA, kt + 2); }
        DOMMA(aB, bB);
    }
#undef LOADA
#undef LOADB
#undef DOMMA

#pragma unroll
    for (int mf = 0; mf < 4; mf++) {
        int r = m0 + wm * 64 + mf * 16 + g;
#pragma unroll
        for (int nf = 0; nf < 4; nf++) {
            int col = n0 + wn * 32 + nf * 8 + 2 * tg;
            float2 v0; v0.x = acc[mf][nf][0]; v0.y = acc[mf][nf][1];
            float2 v1; v1.x = acc[mf][nf][2]; v1.y = acc[mf][nf][3];
            *(float2*)(C + (size_t)r * N + col) = v0;
            *(float2*)(C + (size_t)(r + 8) * N + col) = v1;
        }
    }
}

// ---------------- RoPE on QKV view (row stride 6144) ---------------------------
__global__ void rope_kernel(float* __restrict__ base, int nheads, int total)
{
    int idx = blockIdx.x * blockDim.x + threadIdx.x;
    if (idx >= total) return;
    int j = idx & 63;
    int rem = idx >> 6;
    int h = rem % nheads;
    int bs = rem / nheads;
    int s = bs % SS;

    float inv = expf(-(float)j * (logf(10000.0f) / 64.0f));
    float ang = (float)s * inv;
    float c = cosf(ang), sn = sinf(ang);

    float* p = base + (size_t)bs * NQKV + h * HD;
    float x1 = p[j], x2 = p[j + 64];
    p[j]      = x1 * c - x2 * sn;
    p[j + 64] = x2 * c + x1 * sn;
}

// ---------------- bf16 hi/lo fragment packing for flash ------------------------
// Q: A-frags (m16k16), scaled. out[(bh*128+mt)*8+kc]*64 + lane (hi), +32 (lo)
__global__ __launch_bounds__(256) void pack_q(const float* __restrict__ QKV,
                                              uint4* __restrict__ Qpk)
{
    int idx = blockIdx.x * 256 + threadIdx.x;
    int lane = idx & 31, t = idx >> 5;
    int kc = t & 7; t >>= 3;
    int mt = t & 127; t >>= 7;
    int h = t & 31;
    int b = t >> 5;
    int g = lane >> 2, tg = lane & 3;
    const float scale = 0.08838834764831845f;

    const float* p = QKV + (size_t)(b * SS + mt * 16 + g) * NQKV + h * HD + kc * 16 + 2 * tg;
    float2 v00 = *(const float2*)p;                         // (g,   c)
    float2 v01 = *(const float2*)(p + 8);                   // (g,   c+8)
    float2 v10 = *(const float2*)(p + (size_t)8 * NQKV);    // (g+8, c)
    float2 v11 = *(const float2*)(p + (size_t)8 * NQKV + 8);
    v00.x *= scale; v00.y *= scale; v01.x *= scale; v01.y *= scale;
    v10.x *= scale; v10.y *= scale; v11.x *= scale; v11.y *= scale;

    uint4 hi, lo;
    hi.x = bfpair(v00.x, v00.y); lo.x = bfpair_lo(v00.x, v00.y, hi.x);
    hi.y = bfpair(v10.x, v10.y); lo.y = bfpair_lo(v10.x, v10.y, hi.y);
    hi.z = bfpair(v01.x, v01.y); lo.z = bfpair_lo(v01.x, v01.y, hi.z);
    hi.w = bfpair(v11.x, v11.y); lo.w = bfpair_lo(v11.x, v11.y, hi.w);

    size_t o = ((((size_t)(b * 32 + h) * 128 + mt) * 8 + kc) * 64) + lane;
    Qpk[o] = hi;
    Qpk[o + 32] = lo;
}

// K: B-frags (n8k16) {bh0,bh1,bl0,bl1}. out[((bkv*256+nt)*8+kc)*32+lane]
__global__ __launch_bounds__(256) void pack_k(const float* __restrict__ QKV,
                                              uint4* __restrict__ Kpk)
{
    int idx = blockIdx.x * 256 + threadIdx.x;
    int lane = idx & 31, t = idx >> 5;
    int kc = t & 7; t >>= 3;
    int nt = t & 255; t >>= 8;
    int bkv = t;                    // 0..15
    int b = bkv >> 3, kv = bkv & 7;
    int g = lane >> 2, tg = lane & 3;

    const float* p = QKV + (size_t)(b * SS + nt * 8 + g) * NQKV + 4096 + kv * HD + kc * 16 + 2 * tg;
    float2 v0 = *(const float2*)p;
    float2 v1 = *(const float2*)(p + 8);
    uint4 o;
    o.x = bfpair(v0.x, v0.y);
    o.y = bfpair(v1.x, v1.y);
    o.z = bfpair_lo(v0.x, v0.y, o.x);
    o.w = bfpair_lo(v1.x, v1.y, o.y);
    Kpk[(((size_t)bkv * 256 + nt) * 8 + kc) * 32 + lane] = o;
}

// V^T: B-frags for PV (n = d, k = kv). out[(((bkv*32+vt)*16+nt)*4+kc)*32+lane]
__global__ __launch_bounds__(256) void pack_vt(const float* __restrict__ QKV,
                                               uint4* __restrict__ Vtp)
{
    int idx = blockIdx.x * 256 + threadIdx.x;
    int lane = idx & 31, t = idx >> 5;
    int kc = t & 3; t >>= 2;
    int nt = t & 15; t >>= 4;
    int vt = t & 31; t >>= 5;
    int bkv = t;
    int b = bkv >> 3, kv = bkv & 7;
    int g = lane >> 2, tg = lane & 3;

    int d = nt * 8 + g;
    int r0 = b * SS + vt * 64 + kc * 16 + 2 * tg;
    size_t col = 5120 + kv * HD + d;
    float x0 = QKV[(size_t)r0 * NQKV + col];
    float x1 = QKV[(size_t)(r0 + 1) * NQKV + col];
    float x2 = QKV[(size_t)(r0 + 8) * NQKV + col];
    float x3 = QKV[(size_t)(r0 + 9) * NQKV + col];
    uint4 o;
    o.x = bfpair(x0, x1);
    o.y = bfpair(x2, x3);
    o.z = bfpair_lo(x0, x1, o.x);
    o.w = bfpair_lo(x2, x3, o.y);
    Vtp[((((size_t)bkv * 32 + vt) * 16 + nt) * 4 + kc) * 32 + lane] = o;
}

// ---------------- Flash attention: fragment-direct, no CTA sync ----------------
#define VPITCH 72

__device__ __forceinline__ void split_store(__nv_bfloat16* dh, __nv_bfloat16* dl,
                                            float x0, float x1) {
    __nv_bfloat16 h0 = __float2bfloat16(x0);
    __nv_bfloat16 h1 = __float2bfloat16(x1);
    __nv_bfloat162 hv; hv.x = h0; hv.y = h1;
    __nv_bfloat162 lv;
    lv.x = __float2bfloat16(x0 - __bfloat162float(h0));
    lv.y = __float2bfloat16(x1 - __bfloat162float(h1));
    *(__nv_bfloat162*)dh = hv;
    *(__nv_bfloat162*)dl = lv;
}

__global__ __launch_bounds__(256, 1) void flash_mma(
    const uint4* __restrict__ Qpk, const uint4* __restrict__ Kpk,
    const uint4* __restrict__ Vtp, float* __restrict__ Aout)
{
    __shared__ __nv_bfloat16 Ph[128 * VPITCH];
    __shared__ __nv_bfloat16 Pl[128 * VPITCH];

    int tid = threadIdx.x, lane = tid & 31, wm = tid >> 5;
    int g = lane >> 2, tg = lane & 3;
    int qt = blockIdx.x, h = blockIdx.y, b = blockIdx.z;
    int bkv = b * NKV + (h >> 2);
    int q0 = qt * 128;
    const float NEGINF = __int_as_float(0xff800000);

    // Q fragments in registers (loaded once)
    uint32_t qh[8][4], ql[8][4];
    {
        size_t qbase = (((size_t)(b * 32 + h) * 128 + qt * 8 + wm) * 8) * 64 + lane;
#pragma unroll
        for (int kc = 0; kc < 8; kc++) {
            uint4 hi = Qpk[qbase + (size_t)kc * 64];
            uint4 lo = Qpk[qbase + (size_t)kc * 64 + 32];
            qh[kc][0] = hi.x; qh[kc][1] = hi.y; qh[kc][2] = hi.z; qh[kc][3] = hi.w;
            ql[kc][0] = lo.x; ql[kc][1] = lo.y; ql[kc][2] = lo.z; ql[kc][3] = lo.w;
        }
    }

    float accO[16][4];
#pragma unroll
    for (int nf = 0; nf < 16; nf++)
#pragma unroll
        for (int i = 0; i < 4; i++) accO[nf][i] = 0.f;
    float m0 = NEGINF, m1 = NEGINF, l0 = 0.f, l1 = 0.f;

    const uint4* kBase = Kpk + ((size_t)bkv * 256) * 8 * 32 + lane;
    const uint4* vBase = Vtp + ((size_t)bkv * 32) * 16 * 4 * 32 + lane;

    int nkt = (q0 + wm * 16 + 15) / 64 + 1;   // per-warp causal bound
    for (int kt = 0; kt < nkt; kt++) {
        int k0g = kt * 64;
        float S[8][4];
#pragma unroll
        for (int nf = 0; nf < 8; nf++)
#pragma unroll
            for (int i = 0; i < 4; i++) S[nf][i] = 0.f;

        // S = Q K^T
#pragma unroll
        for (int kc = 0; kc < 8; kc++) {
#pragma unroll
            for (int nf = 0; nf < 8; nf++) {
                uint4 kk = kBase[(((size_t)(kt * 8 + nf)) * 8 + kc) * 32];
                mma_bf16(S[nf], qh[kc], kk.x, kk.y);
                mma_bf16(S[nf], qh[kc], kk.z, kk.w);
                mma_bf16(S[nf], ql[kc], kk.x, kk.y);
            }
        }
        // causal mask
        if (k0g + 63 > q0 + wm * 16) {
            int row0 = q0 + wm * 16 + g, row1 = row0 + 8;
#pragma unroll
            for (int nf = 0; nf < 8; nf++) {
                int col = k0g + nf * 8 + 2 * tg;
                if (col     > row0) S[nf][0] = NEGINF;
                if (col + 1 > row0) S[nf][1] = NEGINF;
                if (col     > row1) S[nf][2] = NEGINF;
                if (col + 1 > row1) S[nf][3] = NEGINF;
            }
        }
        // row max
        float mx0 = NEGINF, mx1 = NEGINF;
#pragma unroll
        for (int nf = 0; nf < 8; nf++) {
            mx0 = fmaxf(mx0, fmaxf(S[nf][0], S[nf][1]));
            mx1 = fmaxf(mx1, fmaxf(S[nf][2], S[nf][3]));
        }
        mx0 = fmaxf(mx0, __shfl_xor_sync(0xffffffff, mx0, 1));
        mx0 = fmaxf(mx0, __shfl_xor_sync(0xffffffff, mx0, 2));
        mx1 = fmaxf(mx1, __shfl_xor_sync(0xffffffff, mx1, 1));
        mx1 = fmaxf(mx1, __shfl_xor_sync(0xffffffff, mx1, 2));
        float m0n = fmaxf(m0, mx0), m1n = fmaxf(m1, mx1);
        float al0 = __expf(m0 - m0n), al1 = __expf(m1 - m1n);
        m0 = m0n; m1 = m1n;

        __syncwarp();   // prev iter's P loads done before overwrite
        float sum0 = 0.f, sum1 = 0.f;
        int pr0 = (wm * 16 + g) * VPITCH, pr1 = (wm * 16 + g + 8) * VPITCH;
#pragma unroll
        for (int nf = 0; nf < 8; nf++) {
            float p00 = __expf(S[nf][0] - m0);
            float p01 = __expf(S[nf][1] - m0);
            float p10 = __expf(S[nf][2] - m1);
            float p11 = __expf(S[nf][3] - m1);
            sum0 += p00 + p01;
            sum1 += p10 + p11;
            int co = nf * 8 + 2 * tg;
            split_store(Ph + pr0 + co, Pl + pr0 + co, p00, p01);
            split_store(Ph + pr1 + co, Pl + pr1 + co, p10, p11);
        }
        sum0 += __shfl_xor_sync(0xffffffff, sum0, 1);
        sum0 += __shfl_xor_sync(0xffffffff, sum0, 2);
        sum1 += __shfl_xor_sync(0xffffffff, sum1, 1);
        sum1 += __shfl_xor_sync(0xffffffff, sum1, 2);
        l0 = l0 * al0 + sum0;
        l1 = l1 * al1 + sum1;
#pragma unroll
        for (int nf = 0; nf < 16; nf++) {
            accO[nf][0] *= al0; accO[nf][1] *= al0;
            accO[nf][2] *= al1; accO[nf][3] *= al1;
        }
        __syncwarp();
        // O += P V
#pragma unroll
        for (int kc = 0; kc < 4; kc++) {
            uint32_t pah[4], pal[4];
            const __nv_bfloat16* pb = Ph + (wm * 16 + g) * VPITCH + kc * 16 + 2 * tg;
            pah[0] = *(const uint32_t*)(pb);
            pah[1] = *(const uint32_t*)(pb + 8 * VPITCH);
            pah[2] = *(const uint32_t*)(pb + 8);
            pah[3] = *(const uint32_t*)(pb + 8 * VPITCH + 8);
            const __nv_bfloat16* pl = Pl + (wm * 16 + g) * VPITCH + kc * 16 + 2 * tg;
            pal[0] = *(const uint32_t*)(pl);
            pal[1] = *(const uint32_t*)(pl + 8 * VPITCH);
            pal[2] = *(const uint32_t*)(pl + 8);
            pal[3] = *(const uint32_t*)(pl + 8 * VPITCH + 8);
#pragma unroll
            for (int nf = 0; nf < 16; nf++) {
                uint4 vv = vBase[((((size_t)kt * 16 + nf) * 4) + kc) * 32];
                mma_bf16(accO[nf], pah, vv.x, vv.y);
                mma_bf16(accO[nf], pah, vv.z, vv.w);
                mma_bf16(accO[nf], pal, vv.x, vv.y);
            }
        }
    }

    // epilogue
    float i0 = 1.0f / l0, i1 = 1.0f / l1;
    int r0 = q0 + wm * 16 + g;
    float* o0 = Aout + (((size_t)b * SS + r0) * NH + h) * HD;
    float* o1 = o0 + (size_t)8 * NH * HD;
#pragma unroll
    for (int nf = 0; nf < 16; nf++) {
        int d = nf * 8 + 2 * tg;
        float2 v0; v0.x = accO[nf][0] * i0; v0.y = accO[nf][1] * i0;
        float2 v1; v1.x = accO[nf][2] * i1; v1.y = accO[nf][3] * i1;
        *(float2*)(o0 + d) = v0;
        *(float2*)(o1 + d) = v1;
    }
}

// ---------------- launch --------------------------------------------------------
extern "C" void kernel_launch(void* const* d_in, const int* in_sizes, int n_in,
                              void* d_out, int out_size)
{
    const float* x  = (const float*)d_in[0];
    const float* wq = (const float*)d_in[1];
    const float* wk = (const float*)d_in[2];
    const float* wv = (const float*)d_in[3];
    const float* wo = (const float*)d_in[4];
    float* out = (float*)d_out;

    float *QKV, *Ap;
    uint32_t *Xp, *Apk, *Wqkvp, *Wop;
    uint4 *Qpk, *Kpk, *Vtp;
    cudaGetSymbolAddress((void**)&QKV, g_QKV);
    cudaGetSymbolAddress((void**)&Ap, g_A);
    cudaGetSymbolAddress((void**)&Xp, g_Xp);
    cudaGetSymbolAddress((void**)&Apk, g_Apk);
    cudaGetSymbolAddress((void**)&Wqkvp, g_Wqkvp);
    cudaGetSymbolAddress((void**)&Wop, g_Wop);
    cudaGetSymbolAddress((void**)&Qpk, g_Qpk);
    cudaGetSymbolAddress((void**)&Kpk, g_Kpk);
    cudaGetSymbolAddress((void**)&Vtp, g_Vtp);

    const int KT = HIDDEN / 8;   // 512

    // pack GEMM operands (tf32, fragment-major)
    pack_a<<<(MROWS/16)*(HIDDEN/8)*32/256, 256>>>(x, Xp, MROWS, HIDDEN);
    pack_b<<<((NH*HD)/8)*KT*32/256, 256>>>(wq, Wqkvp, NH*HD, HIDDEN);
    pack_b<<<((NKV*HD)/8)*KT*32/256, 256>>>(wk, Wqkvp + (size_t)512*KT*32*2, NKV*HD, HIDDEN);
    pack_b<<<((NKV*HD)/8)*KT*32/256, 256>>>(wv, Wqkvp + (size_t)640*KT*32*2, NKV*HD, HIDDEN);
    pack_b<<<(HIDDEN/8)*((NH*HD)/8)*32/256, 256>>>(wo, Wop, HIDDEN, NH*HD);

    // fused QKV projection (N=6144)
    gemm_fp<<<dim3(NQKV/128, MROWS/128), 256>>>(Xp, Wqkvp, QKV, MROWS, NQKV, HIDDEN);

    // RoPE on Q and K regions of QKV
    rope_kernel<<<(MROWS*NH*64 + 255)/256, 256>>>(QKV, NH, MROWS*NH*64);
    rope_kernel<<<(MROWS*NKV*64 + 255)/256, 256>>>(QKV + 4096, NKV, MROWS*NKV*64);

    // bf16 hi/lo fragment packs for flash
    pack_q<<<BB*NH*128*8*32/256, 256>>>(QKV, Qpk);
    pack_k<<<BB*NKV*256*8*32/256, 256>>>(QKV, Kpk);
    pack_vt<<<BB*NKV*32*16*4*32/256, 256>>>(QKV, Vtp);

    // flash attention (fragment-direct)
    flash_mma<<<dim3(SS/128, NH, BB), 256>>>(Qpk, Kpk, Vtp, Ap);

    // output projection
    pack_a<<<(MROWS/16)*((NH*HD)/8)*32/256, 256>>>(Ap, Apk, MROWS, NH*HD);
    gemm_fp<<<dim3(HIDDEN/128, MROWS/128), 256>>>(Apk, Wop, out, MROWS, HIDDEN, NH*HD);
}

// round 11
// speedup vs baseline: 4.2789x; 1.0118x over previous
#include <cuda_runtime.h>
#include <cuda_bf16.h>
#include <math.h>
#include <stdint.h>

#define HIDDEN 4096
#define NH 32
#define NKV 8
#define HD 128
#define BB 2
#define SS 2048
#define MROWS (BB*SS)   /* 4096 */
#define NQKV 6144       /* 4096 + 1024 + 1024 */

// ---------------- scratch -----------------------------------------------------
__device__ float g_QKV[(size_t)MROWS * NQKV];          // [bs][q 4096 | k 1024 | v 1024]
__device__ float g_A[(size_t)MROWS * NH * HD];
__device__ uint32_t g_Xp   [(size_t)MROWS * HIDDEN];
__device__ uint32_t g_Apk  [(size_t)MROWS * NH * HD];
__device__ uint32_t g_Wqkvp[(size_t)NQKV * HIDDEN];
__device__ uint32_t g_Wop  [(size_t)HIDDEN * NH * HD];
__device__ uint4 g_Qpk[(size_t)BB * NH * 128 * 8 * 64];
__device__ uint4 g_Kpk[(size_t)BB * NKV * 256 * 8 * 32];
__device__ uint4 g_Vtp[(size_t)BB * NKV * 32 * 16 * 4 * 32];

__device__ __forceinline__ uint32_t f2tf32(float f) {
    uint32_t r; asm("cvt.rna.tf32.f32 %0, %1;" : "=r"(r) : "f"(f)); return r;
}
__device__ __forceinline__ uint32_t bfpair(float x0, float x1) {
    __nv_bfloat162 h; h.x = __float2bfloat16(x0); h.y = __float2bfloat16(x1);
    return *(uint32_t*)&h;
}
__device__ __forceinline__ uint32_t bfpair_lo(float x0, float x1, uint32_t hi) {
    __nv_bfloat162 h = *(__nv_bfloat162*)&hi;
    return bfpair(x0 - __bfloat162float(h.x), x1 - __bfloat162float(h.y));
}

__device__ __forceinline__ void mma16n8k8(float* d, const uint32_t* a,
                                          uint32_t b0, uint32_t b1) {
    asm volatile(
        "mma.sync.aligned.m16n8k8.row.col.f32.tf32.tf32.f32 "
        "{%0,%1,%2,%3}, {%4,%5,%6,%7}, {%8,%9}, {%0,%1,%2,%3};"
        : "+f"(d[0]), "+f"(d[1]), "+f"(d[2]), "+f"(d[3])
        : "r"(a[0]), "r"(a[1]), "r"(a[2]), "r"(a[3]), "r"(b0), "r"(b1));
}
__device__ __forceinline__ void mma_bf16(float* d, const uint32_t* a,
                                         uint32_t b0, uint32_t b1) {
    asm volatile(
        "mma.sync.aligned.m16n8k16.row.col.f32.bf16.bf16.f32 "
        "{%0,%1,%2,%3}, {%4,%5,%6,%7}, {%8,%9}, {%0,%1,%2,%3};"
        : "+f"(d[0]), "+f"(d[1]), "+f"(d[2]), "+f"(d[3])
        : "r"(a[0]), "r"(a[1]), "r"(a[2]), "r"(a[3]), "r"(b0), "r"(b1));
}

// ---------------- tf32 packing (GEMM operands) ---------------------------------
__global__ __launch_bounds__(256) void pack_a(const float* __restrict__ X,
                                              uint32_t* __restrict__ Xp,
                                              int M, int K)
{
    int idx = blockIdx.x * 256 + threadIdx.x;
    int total = (M >> 4) * (K >> 3) * 32;
    if (idx >= total) return;
    int lane = idx & 31, t = idx >> 5;
    int KT = K >> 3;
    int kt = t % KT, mt = t / KT;
    int g = lane >> 2, tg = lane & 3;
    size_t r0 = (size_t)(mt * 16 + g) * K + kt * 8 + tg;
    uint4 v;
    v.x = f2tf32(X[r0]);
    v.y = f2tf32(X[r0 + (size_t)8 * K]);
    v.z = f2tf32(X[r0 + 4]);
    v.w = f2tf32(X[r0 + (size_t)8 * K + 4]);
    ((uint4*)Xp)[(size_t)t * 32 + lane] = v;
}

__global__ __launch_bounds__(256) void pack_b(const float* __restrict__ W,
                                              uint32_t* __restrict__ Wp,
                                              int N, int K)
{
    int idx = blockIdx.x * 256 + threadIdx.x;
    int total = (N >> 3) * (K >> 3) * 32;
    if (idx >= total) return;
    int lane = idx & 31, t = idx >> 5;
    int KT = K >> 3;
    int kt = t % KT, nt = t / KT;
    int g = lane >> 2, tg = lane & 3;
    size_t r0 = (size_t)(nt * 8 + g) * K + kt * 8 + tg;
    uint2 v;
    v.x = f2tf32(W[r0]);
    v.y = f2tf32(W[r0 + 4]);
    ((uint2*)Wp)[(size_t)t * 32 + lane] = v;
}

// ---------------- persistent fragment-direct TF32 GEMM: C = A * W^T ------------
__global__ __launch_bounds__(256, 2) void gemm_fp(
    const uint32_t* __restrict__ Apk, const uint32_t* __restrict__ Bp,
    float* __restrict__ C, int M, int N, int K)
{
    int tid = threadIdx.x;
    int lane = tid & 31, wid = tid >> 5;
    int wm = wid & 1, wn = wid >> 1;
    int g = lane >> 2, tg = lane & 3;
    const int KT = K >> 3;
    const int ntn = N >> 7;
    const int ntiles = (M >> 7) * ntn;
    const size_t aStep = (size_t)KT * 32;
    const size_t bStep = (size_t)KT * 32;

    for (int tIdx = blockIdx.x; tIdx < ntiles; tIdx += gridDim.x) {
        int m0 = (tIdx / ntn) << 7;
        int n0 = (tIdx % ntn) << 7;

        const uint4* aP = (const uint4*)Apk + ((size_t)((m0 >> 4) + wm * 4) * KT) * 32 + lane;
        const uint2* bP = (const uint2*)Bp + ((size_t)((n0 >> 3) + wn * 4) * KT) * 32 + lane;

        float acc[4][4][4];
#pragma unroll
        for (int mf = 0; mf < 4; mf++)
#pragma unroll
            for (int nf = 0; nf < 4; nf++)
#pragma unroll
                for (int i = 0; i < 4; i++) acc[mf][nf][i] = 0.f;

#define LOADA(dst, kt) do { \
        _Pragma("unroll") \
        for (int mf = 0; mf < 4; mf++) { \
            uint4 u = aP[(size_t)mf * aStep + (size_t)(kt) * 32]; \
            dst[mf][0] = u.x; dst[mf][1] = u.y; dst[mf][2] = u.z; dst[mf][3] = u.w; \
        } \
    } while (0)
#define LOADB(dst, kt) do { \
        _Pragma("unroll") \
        for (int nf = 0; nf < 4; nf++) { \
            uint2 u = bP[(size_t)nf * bStep + (size_t)(kt) * 32]; \
            dst[nf][0] = u.x; dst[nf][1] = u.y; \
        } \
    } while (0)
#define DOMMA(a, b) do { \
        _Pragma("unroll") \
        for (int nf = 0; nf < 4; nf++) \
            _Pragma("unroll") \
            for (int mf = 0; mf < 4; mf++) \
                mma16n8k8(acc[mf][nf], a[mf], b[nf][0], b[nf][1]); \
    } while (0)

        uint32_t aA[4][4], aB[4][4], bA[4][2], bB[4][2];
        LOADA(aA, 0); LOADB(bA, 0);
        for (int kt = 0; kt < KT; kt += 2) {
            LOADA(aB, kt + 1); LOADB(bB, kt + 1);
            DOMMA(aA, bA);
            if (kt + 2 < KT) { LOADA(aA, kt + 2); LOADB(bA, kt + 2); }
            DOMMA(aB, bB);
        }
#undef LOADA
#undef LOADB
#undef DOMMA

#pragma unroll
        for (int mf = 0; mf < 4; mf++) {
            int r = m0 + wm * 64 + mf * 16 + g;
#pragma unroll
            for (int nf = 0; nf < 4; nf++) {
                int col = n0 + wn * 32 + nf * 8 + 2 * tg;
                float2 v0; v0.x = acc[mf][nf][0]; v0.y = acc[mf][nf][1];
                float2 v1; v1.x = acc[mf][nf][2]; v1.y = acc[mf][nf][3];
                *(float2*)(C + (size_t)r * N + col) = v0;
                *(float2*)(C + (size_t)(r + 8) * N + col) = v1;
            }
        }
    }
}

// ---------------- bf16 hi/lo fragment packing with fused RoPE ------------------
// rope(c): j=c&63; v = a*cos(s*inv_j) + sgn*partner*sin(s*inv_j), sgn=-1 if c<64
// inv_j computed exactly as the old rope kernel: expf(-j * (logf(10000)/64))

// Q: A-frags (m16k16), rope + scale.
__global__ __launch_bounds__(256) void pack_q(const float* __restrict__ QKV,
                                              uint4* __restrict__ Qpk)
{
    int idx = blockIdx.x * 256 + threadIdx.x;
    int lane = idx & 31, t = idx >> 5;
    int kc = t & 7; t >>= 3;
    int mt = t & 127; t >>= 7;
    int h = t & 31;
    int b = t >> 5;
    int g = lane >> 2, tg = lane & 3;
    const float scale = 0.08838834764831845f;
    const float ropeL = logf(10000.0f) / 64.0f;

    int c0 = kc * 16 + 2 * tg;
    int cp = c0 ^ 64;
    int s0 = mt * 16 + g;
    float sgn = (kc < 4) ? -1.f : 1.f;

    const float* base0 = QKV + (size_t)(b * SS + s0) * NQKV + h * HD;
    const float* base1 = base0 + (size_t)8 * NQKV;
    float2 a00 = *(const float2*)(base0 + c0);
    float2 a01 = *(const float2*)(base0 + c0 + 8);
    float2 p00 = *(const float2*)(base0 + cp);
    float2 p01 = *(const float2*)(base0 + cp + 8);
    float2 a10 = *(const float2*)(base1 + c0);
    float2 a11 = *(const float2*)(base1 + c0 + 8);
    float2 p10 = *(const float2*)(base1 + cp);
    float2 p11 = *(const float2*)(base1 + cp + 8);

    int jb = c0 & 63;
    float i0 = expf(-(float)jb * ropeL);
    float i1 = expf(-(float)(jb + 1) * ropeL);
    float i8 = expf(-(float)(jb + 8) * ropeL);
    float i9 = expf(-(float)(jb + 9) * ropeL);

    float sA = (float)s0, sB = (float)(s0 + 8);
    float v00x = (a00.x * cosf(sA * i0) + sgn * p00.x * sinf(sA * i0)) * scale;
    float v00y = (a00.y * cosf(sA * i1) + sgn * p00.y * sinf(sA * i1)) * scale;
    float v01x = (a01.x * cosf(sA * i8) + sgn * p01.x * sinf(sA * i8)) * scale;
    float v01y = (a01.y * cosf(sA * i9) + sgn * p01.y * sinf(sA * i9)) * scale;
    float v10x = (a10.x * cosf(sB * i0) + sgn * p10.x * sinf(sB * i0)) * scale;
    float v10y = (a10.y * cosf(sB * i1) + sgn * p10.y * sinf(sB * i1)) * scale;
    float v11x = (a11.x * cosf(sB * i8) + sgn * p11.x * sinf(sB * i8)) * scale;
    float v11y = (a11.y * cosf(sB * i9) + sgn * p11.y * sinf(sB * i9)) * scale;

    uint4 hi, lo;
    hi.x = bfpair(v00x, v00y); lo.x = bfpair_lo(v00x, v00y, hi.x);
    hi.y = bfpair(v10x, v10y); lo.y = bfpair_lo(v10x, v10y, hi.y);
    hi.z = bfpair(v01x, v01y); lo.z = bfpair_lo(v01x, v01y, hi.z);
    hi.w = bfpair(v11x, v11y); lo.w = bfpair_lo(v11x, v11y, hi.w);

    size_t o = ((((size_t)(b * 32 + h) * 128 + mt) * 8 + kc) * 64) + lane;
    Qpk[o] = hi;
    Qpk[o + 32] = lo;
}

// K: B-frags (n8k16) with fused rope.
__global__ __launch_bounds__(256) void pack_k(const float* __restrict__ QKV,
                                              uint4* __restrict__ Kpk)
{
    int idx = blockIdx.x * 256 + threadIdx.x;
    int lane = idx & 31, t = idx >> 5;
    int kc = t & 7; t >>= 3;
    int nt = t & 255; t >>= 8;
    int bkv = t;
    int b = bkv >> 3, kv = bkv & 7;
    int g = lane >> 2, tg = lane & 3;
    const float ropeL = logf(10000.0f) / 64.0f;

    int c0 = kc * 16 + 2 * tg;
    int cp = c0 ^ 64;
    int s0 = nt * 8 + g;
    float sgn = (kc < 4) ? -1.f : 1.f;

    const float* base = QKV + (size_t)(b * SS + s0) * NQKV + 4096 + kv * HD;
    float2 a0 = *(const float2*)(base + c0);
    float2 a1 = *(const float2*)(base + c0 + 8);
    float2 p0 = *(const float2*)(base + cp);
    float2 p1 = *(const float2*)(base + cp + 8);

    int jb = c0 & 63;
    float i0 = expf(-(float)jb * ropeL);
    float i1 = expf(-(float)(jb + 1) * ropeL);
    float i8 = expf(-(float)(jb + 8) * ropeL);
    float i9 = expf(-(float)(jb + 9) * ropeL);
    float s = (float)s0;

    float v0x = a0.x * cosf(s * i0) + sgn * p0.x * sinf(s * i0);
    float v0y = a0.y * cosf(s * i1) + sgn * p0.y * sinf(s * i1);
    float v1x = a1.x * cosf(s * i8) + sgn * p1.x * sinf(s * i8);
    float v1y = a1.y * cosf(s * i9) + sgn * p1.y * sinf(s * i9);

    uint4 o;
    o.x = bfpair(v0x, v0y);
    o.y = bfpair(v1x, v1y);
    o.z = bfpair_lo(v0x, v0y, o.x);
    o.w = bfpair_lo(v1x, v1y, o.y);
    Kpk[(((size_t)bkv * 256 + nt) * 8 + kc) * 32 + lane] = o;
}

// V^T: B-frags for PV (no rope).
__global__ __launch_bounds__(256) void pack_vt(const float* __restrict__ QKV,
                                               uint4* __restrict__ Vtp)
{
    int idx = blockIdx.x * 256 + threadIdx.x;
    int lane = idx & 31, t = idx >> 5;
    int kc = t & 3; t >>= 2;
    int nt = t & 15; t >>= 4;
    int vt = t & 31; t >>= 5;
    int bkv = t;
    int b = bkv >> 3, kv = bkv & 7;
    int g = lane >> 2, tg = lane & 3;

    int d = nt * 8 + g;
    int r0 = b * SS + vt * 64 + kc * 16 + 2 * tg;
    size_t col = 5120 + kv * HD + d;
    float x0 = QKV[(size_t)r0 * NQKV + col];
    float x1 = QKV[(size_t)(r0 + 1) * NQKV + col];
    float x2 = QKV[(size_t)(r0 + 8) * NQKV + col];
    float x3 = QKV[(size_t)(r0 + 9) * NQKV + col];
    uint4 o;
    o.x = bfpair(x0, x1);
    o.y = bfpair(x2, x3);
    o.z = bfpair_lo(x0, x1, o.x);
    o.w = bfpair_lo(x2, x3, o.y);
    Vtp[((((size_t)bkv * 32 + vt) * 16 + nt) * 4 + kc) * 32 + lane] = o;
}

// ---------------- Flash attention: fragment-direct, no CTA sync ----------------
#define VPITCH 72

__device__ __forceinline__ void split_store(__nv_bfloat16* dh, __nv_bfloat16* dl,
                                            float x0, float x1) {
    __nv_bfloat16 h0 = __float2bfloat16(x0);
    __nv_bfloat16 h1 = __float2bfloat16(x1);
    __nv_bfloat162 hv; hv.x = h0; hv.y = h1;
    __nv_bfloat162 lv;
    lv.x = __float2bfloat16(x0 - __bfloat162float(h0));
    lv.y = __float2bfloat16(x1 - __bfloat162float(h1));
    *(__nv_bfloat162*)dh = hv;
    *(__nv_bfloat162*)dl = lv;
}

__global__ __launch_bounds__(256, 1) void flash_mma(
    const uint4* __restrict__ Qpk, const uint4* __restrict__ Kpk,
    const uint4* __restrict__ Vtp, float* __restrict__ Aout)
{
    __shared__ __nv_bfloat16 Ph[128 * VPITCH];
    __shared__ __nv_bfloat16 Pl[128 * VPITCH];

    int tid = threadIdx.x, lane = tid & 31, wm = tid >> 5;
    int g = lane >> 2, tg = lane & 3;
    int qt = blockIdx.x, h = blockIdx.y, b = blockIdx.z;
    int bkv = b * NKV + (h >> 2);
    int q0 = qt * 128;
    const float NEGINF = __int_as_float(0xff800000);

    uint32_t qh[8][4], ql[8][4];
    {
        size_t qbase = (((size_t)(b * 32 + h) * 128 + qt * 8 + wm) * 8) * 64 + lane;
#pragma unroll
        for (int kc = 0; kc < 8; kc++) {
            uint4 hi = Qpk[qbase + (size_t)kc * 64];
            uint4 lo = Qpk[qbase + (size_t)kc * 64 + 32];
            qh[kc][0] = hi.x; qh[kc][1] = hi.y; qh[kc][2] = hi.z; qh[kc][3] = hi.w;
            ql[kc][0] = lo.x; ql[kc][1] = lo.y; ql[kc][2] = lo.z; ql[kc][3] = lo.w;
        }
    }

    float accO[16][4];
#pragma unroll
    for (int nf = 0; nf < 16; nf++)
#pragma unroll
        for (int i = 0; i < 4; i++) accO[nf][i] = 0.f;
    float m0 = NEGINF, m1 = NEGINF, l0 = 0.f, l1 = 0.f;

    const uint4* kBase = Kpk + ((size_t)bkv * 256) * 8 * 32 + lane;
    const uint4* vBase = Vtp + ((size_t)bkv * 32) * 16 * 4 * 32 + lane;

    int nkt = (q0 + wm * 16 + 15) / 64 + 1;
    for (int kt = 0; kt < nkt; kt++) {
        int k0g = kt * 64;
        float S[8][4];
#pragma unroll
        for (int nf = 0; nf < 8; nf++)
#pragma unroll
            for (int i = 0; i < 4; i++) S[nf][i] = 0.f;

#pragma unroll
        for (int kc = 0; kc < 8; kc++) {
#pragma unroll
            for (int nf = 0; nf < 8; nf++) {
                uint4 kk = kBase[(((size_t)(kt * 8 + nf)) * 8 + kc) * 32];
                mma_bf16(S[nf], qh[kc], kk.x, kk.y);
                mma_bf16(S[nf], qh[kc], kk.z, kk.w);
                mma_bf16(S[nf], ql[kc], kk.x, kk.y);
            }
        }
        if (k0g + 63 > q0 + wm * 16) {
            int row0 = q0 + wm * 16 + g, row1 = row0 + 8;
#pragma unroll
            for (int nf = 0; nf < 8; nf++) {
                int col = k0g + nf * 8 + 2 * tg;
                if (col     > row0) S[nf][0] = NEGINF;
                if (col + 1 > row0) S[nf][1] = NEGINF;
                if (col     > row1) S[nf][2] = NEGINF;
                if (col + 1 > row1) S[nf][3] = NEGINF;
            }
        }
        float mx0 = NEGINF, mx1 = NEGINF;
#pragma unroll
        for (int nf = 0; nf < 8; nf++) {
            mx0 = fmaxf(mx0, fmaxf(S[nf][0], S[nf][1]));
            mx1 = fmaxf(mx1, fmaxf(S[nf][2], S[nf][3]));
        }
        mx0 = fmaxf(mx0, __shfl_xor_sync(0xffffffff, mx0, 1));
        mx0 = fmaxf(mx0, __shfl_xor_sync(0xffffffff, mx0, 2));
        mx1 = fmaxf(mx1, __shfl_xor_sync(0xffffffff, mx1, 1));
        mx1 = fmaxf(mx1, __shfl_xor_sync(0xffffffff, mx1, 2));
        float m0n = fmaxf(m0, mx0), m1n = fmaxf(m1, mx1);
        float al0 = __expf(m0 - m0n), al1 = __expf(m1 - m1n);
        m0 = m0n; m1 = m1n;

        __syncwarp();
        float sum0 = 0.f, sum1 = 0.f;
        int pr0 = (wm * 16 + g) * VPITCH, pr1 = (wm * 16 + g + 8) * VPITCH;
#pragma unroll
        for (int nf = 0; nf < 8; nf++) {
            float p00 = __expf(S[nf][0] - m0);
            float p01 = __expf(S[nf][1] - m0);
            float p10 = __expf(S[nf][2] - m1);
            float p11 = __expf(S[nf][3] - m1);
            sum0 += p00 + p01;
            sum1 += p10 + p11;
            int co = nf * 8 + 2 * tg;
            split_store(Ph + pr0 + co, Pl + pr0 + co, p00, p01);
            split_store(Ph + pr1 + co, Pl + pr1 + co, p10, p11);
        }
        sum0 += __shfl_xor_sync(0xffffffff, sum0, 1);
        sum0 += __shfl_xor_sync(0xffffffff, sum0, 2);
        sum1 += __shfl_xor_sync(0xffffffff, sum1, 1);
        sum1 += __shfl_xor_sync(0xffffffff, sum1, 2);
        l0 = l0 * al0 + sum0;
        l1 = l1 * al1 + sum1;
#pragma unroll
        for (int nf = 0; nf < 16; nf++) {
            accO[nf][0] *= al0; accO[nf][1] *= al0;
            accO[nf][2] *= al1; accO[nf][3] *= al1;
        }
        __syncwarp();
#pragma unroll
        for (int kc = 0; kc < 4; kc++) {
            uint32_t pah[4], pal[4];
            const __nv_bfloat16* pb = Ph + (wm * 16 + g) * VPITCH + kc * 16 + 2 * tg;
            pah[0] = *(const uint32_t*)(pb);
            pah[1] = *(const uint32_t*)(pb + 8 * VPITCH);
            pah[2] = *(const uint32_t*)(pb + 8);
            pah[3] = *(const uint32_t*)(pb + 8 * VPITCH + 8);
            const __nv_bfloat16* pl = Pl + (wm * 16 + g) * VPITCH + kc * 16 + 2 * tg;
            pal[0] = *(const uint32_t*)(pl);
            pal[1] = *(const uint32_t*)(pl + 8 * VPITCH);
            pal[2] = *(const uint32_t*)(pl + 8);
            pal[3] = *(const uint32_t*)(pl + 8 * VPITCH + 8);
#pragma unroll
            for (int nf = 0; nf < 16; nf++) {
                uint4 vv = vBase[((((size_t)kt * 16 + nf) * 4) + kc) * 32];
                mma_bf16(accO[nf], pah, vv.x, vv.y);
                mma_bf16(accO[nf], pah, vv.z, vv.w);
                mma_bf16(accO[nf], pal, vv.x, vv.y);
            }
        }
    }

    float i0 = 1.0f / l0, i1 = 1.0f / l1;
    int r0 = q0 + wm * 16 + g;
    float* o0 = Aout + (((size_t)b * SS + r0) * NH + h) * HD;
    float* o1 = o0 + (size_t)8 * NH * HD;
#pragma unroll
    for (int nf = 0; nf < 16; nf++) {
        int d = nf * 8 + 2 * tg;
        float2 v0; v0.x = accO[nf][0] * i0; v0.y = accO[nf][1] * i0;
        float2 v1; v1.x = accO[nf][2] * i1; v1.y = accO[nf][3] * i1;
        *(float2*)(o0 + d) = v0;
        *(float2*)(o1 + d) = v1;
    }
}

// ---------------- launch --------------------------------------------------------
extern "C" void kernel_launch(void* const* d_in, const int* in_sizes, int n_in,
                              void* d_out, int out_size)
{
    const float* x  = (const float*)d_in[0];
    const float* wq = (const float*)d_in[1];
    const float* wk = (const float*)d_in[2];
    const float* wv = (const float*)d_in[3];
    const float* wo = (const float*)d_in[4];
    float* out = (float*)d_out;

    float *QKV, *Ap;
    uint32_t *Xp, *Apk, *Wqkvp, *Wop;
    uint4 *Qpk, *Kpk, *Vtp;
    cudaGetSymbolAddress((void**)&QKV, g_QKV);
    cudaGetSymbolAddress((void**)&Ap, g_A);
    cudaGetSymbolAddress((void**)&Xp, g_Xp);
    cudaGetSymbolAddress((void**)&Apk, g_Apk);
    cudaGetSymbolAddress((void**)&Wqkvp, g_Wqkvp);
    cudaGetSymbolAddress((void**)&Wop, g_Wop);
    cudaGetSymbolAddress((void**)&Qpk, g_Qpk);
    cudaGetSymbolAddress((void**)&Kpk, g_Kpk);
    cudaGetSymbolAddress((void**)&Vtp, g_Vtp);

    int smcount = 148;
    cudaDeviceGetAttribute(&smcount, cudaDevAttrMultiProcessorCount, 0);
    int pgrid = 2 * smcount;

    const int KT = HIDDEN / 8;   // 512

    // pack GEMM operands
    pack_a<<<(MROWS/16)*(HIDDEN/8)*32/256, 256>>>(x, Xp, MROWS, HIDDEN);
    pack_b<<<((NH*HD)/8)*KT*32/256, 256>>>(wq, Wqkvp, NH*HD, HIDDEN);
    pack_b<<<((NKV*HD)/8)*KT*32/256, 256>>>(wk, Wqkvp + (size_t)512*KT*32*2, NKV*HD, HIDDEN);
    pack_b<<<((NKV*HD)/8)*KT*32/256, 256>>>(wv, Wqkvp + (size_t)640*KT*32*2, NKV*HD, HIDDEN);

    // fused QKV projection (persistent grid)
    gemm_fp<<<pgrid, 256>>>(Xp, Wqkvp, QKV, MROWS, NQKV, HIDDEN);

    // bf16 hi/lo fragment packs (RoPE fused into Q/K packs)
    pack_q<<<BB*NH*128*8*32/256, 256>>>(QKV, Qpk);
    pack_k<<<BB*NKV*256*8*32/256, 256>>>(QKV, Kpk);
    pack_vt<<<BB*NKV*32*16*4*32/256, 256>>>(QKV, Vtp);

    // flash attention
    flash_mma<<<dim3(SS/128, NH, BB), 256>>>(Qpk, Kpk, Vtp, Ap);

    // output projection
    pack_b<<<(HIDDEN/8)*((NH*HD)/8)*32/256, 256>>>(wo, Wop, HIDDEN, NH*HD);
    pack_a<<<(MROWS/16)*((NH*HD)/8)*32/256, 256>>>(Ap, Apk, MROWS, NH*HD);
    gemm_fp<<<pgrid, 256>>>(Apk, Wop, out, MROWS, HIDDEN, NH*HD);
}